// round 1
// baseline (speedup 1.0000x reference)
#include <cuda_runtime.h>
#include <cuda_bf16.h>
#include <math.h>

// Problem constants
#define D_MODEL 2048
#define N_HEADS 16
#define D_CQ    1536
#define D_C     512
#define D_H     128
#define D_R     64
#define BSZ     4
#define SEQ     2048
#define NTOK    (BSZ*SEQ)            // 8192
#define D_QK    (D_H + D_R)          // 192

// ---------------- scratch (alloc-free: __device__ globals) ----------------
__device__ float g_tmp1[(long long)NTOK * D_CQ];
__device__ float g_cQ  [(long long)NTOK * D_CQ];
__device__ float g_qC  [(long long)NTOK * (N_HEADS*D_H)];
__device__ float g_qR  [(long long)NTOK * (N_HEADS*D_R)];
__device__ float g_kr  [(long long)NTOK * D_R];
__device__ float g_krn [(long long)NTOK * D_R];
__device__ float g_tmp2[(long long)NTOK * D_C];
__device__ float g_cKV [(long long)NTOK * D_C];
__device__ float g_kC  [(long long)NTOK * (N_HEADS*D_H)];
__device__ float g_vC  [(long long)NTOK * (N_HEADS*D_H)];
__device__ float g_qf  [(long long)NTOK * N_HEADS * D_QK];
__device__ float g_kf  [(long long)NTOK * N_HEADS * D_QK];
__device__ float g_attn[(long long)NTOK * (N_HEADS*D_H)];

// ---------------- generic tiled SGEMM ----------------
// C = A(MxK) * B + bias;  TB=false: B is KxN (NN);  TB=true: B is NxK (NT, C=A*B^T)
// Batched via blockIdx.z with composite strides: off = (z/IC)*so + (z%IC)*si
// Assumes: M%64==0, N%64==0, K%16==0, all ld's %4==0, 16B-aligned bases.
template<bool TB>
__global__ __launch_bounds__(256)
void gemm_kernel(const float* __restrict__ A, const float* __restrict__ Bm,
                 const float* __restrict__ bias, float* __restrict__ C,
                 int M, int N, int K, int lda, int ldb, int ldc,
                 long long soA, long long siA,
                 long long soB, long long siB,
                 long long soC, long long siC, int IC)
{
    int z = blockIdx.z;
    long long zo = (long long)(z / IC), zi = (long long)(z % IC);
    const float* Ab = A  + zo*soA + zi*siA;
    const float* Bb = Bm + zo*soB + zi*siB;
    float*       Cb = C  + zo*soC + zi*siC;

    int m0 = blockIdx.y * 64;
    int n0 = blockIdx.x * 64;

    __shared__ float sA[16][68];
    __shared__ float sB[16][68];

    int tid = threadIdx.x;
    int ty = tid >> 4, tx = tid & 15;

    float acc[4][4] = {};

    int arow = tid >> 2;          // 0..63
    int ak   = (tid & 3) * 4;     // 0,4,8,12

    int brow = tid >> 4;          // 0..15 (NN)
    int bcol = (tid & 15) * 4;    // 0..60 (NN)

    for (int k0 = 0; k0 < K; k0 += 16) {
        float4 a4 = *(const float4*)(Ab + (long long)(m0 + arow) * lda + k0 + ak);
        sA[ak+0][arow] = a4.x; sA[ak+1][arow] = a4.y;
        sA[ak+2][arow] = a4.z; sA[ak+3][arow] = a4.w;

        if (TB) {
            float4 b4 = *(const float4*)(Bb + (long long)(n0 + arow) * ldb + k0 + ak);
            sB[ak+0][arow] = b4.x; sB[ak+1][arow] = b4.y;
            sB[ak+2][arow] = b4.z; sB[ak+3][arow] = b4.w;
        } else {
            float4 b4 = *(const float4*)(Bb + (long long)(k0 + brow) * ldb + n0 + bcol);
            *(float4*)&sB[brow][bcol] = b4;
        }
        __syncthreads();

        #pragma unroll
        for (int kk = 0; kk < 16; kk++) {
            float af[4], bf[4];
            *(float4*)af = *(const float4*)&sA[kk][ty*4];
            *(float4*)bf = *(const float4*)&sB[kk][tx*4];
            #pragma unroll
            for (int i = 0; i < 4; i++)
                #pragma unroll
                for (int j = 0; j < 4; j++)
                    acc[i][j] = fmaf(af[i], bf[j], acc[i][j]);
        }
        __syncthreads();
    }

    #pragma unroll
    for (int i = 0; i < 4; i++) {
        int m = m0 + ty*4 + i;
        #pragma unroll
        for (int j = 0; j < 4; j++) {
            int n = n0 + tx*4 + j;
            float b = bias ? bias[n] : 0.0f;
            Cb[(long long)m * ldc + n] = acc[i][j] + b;
        }
    }
}

// ---------------- rmsnorm (one block per row) ----------------
__global__ __launch_bounds__(256)
void rmsnorm_kernel(const float* __restrict__ x, const float* __restrict__ g,
                    float* __restrict__ y, int dim)
{
    long long base = (long long)blockIdx.x * dim;
    int tid = threadIdx.x;
    float s = 0.0f;
    for (int i = tid; i < dim; i += 256) {
        float v = x[base + i];
        s += v * v;
    }
    __shared__ float red[256];
    red[tid] = s; __syncthreads();
    for (int st = 128; st > 0; st >>= 1) {
        if (tid < st) red[tid] += red[tid + st];
        __syncthreads();
    }
    float rs = rsqrtf(red[0] / (float)dim + 1e-6f);
    for (int i = tid; i < dim; i += 256)
        y[base + i] = x[base + i] * rs * g[i];
}

// ---------------- pack q_full/k_full with RoPE ----------------
// q_full[bs,h,0:128]=qC ; q_full[bs,h,128:192]=rope(qR)
// k_full[bs,h,0:64]=rope(rmsnorm(kr)) broadcast; k_full[bs,h,64:192]=kC
__global__ __launch_bounds__(256)
void pack_kernel(const float* __restrict__ qC, const float* __restrict__ qR,
                 const float* __restrict__ krn, const float* __restrict__ kC,
                 const float* __restrict__ freqs,
                 float* __restrict__ qf, float* __restrict__ kf)
{
    int bs = blockIdx.x;
    int s  = bs & (SEQ - 1);
    long long qfb = (long long)bs * N_HEADS * D_QK;
    int tid = threadIdx.x;

    __shared__ float krs[D_R];
    if (tid < 32) {
        int i = tid;
        float a = krn[(long long)bs*D_R + 2*i];
        float b = krn[(long long)bs*D_R + 2*i + 1];
        float c  = freqs[(long long)s*D_R + 2*i];
        float sn = freqs[(long long)s*D_R + 2*i + 1];
        krs[2*i]   = a*c - b*sn;
        krs[2*i+1] = a*sn + b*c;
    }
    __syncthreads();

    // qC -> q_full[0:128]
    for (int idx = tid; idx < N_HEADS*D_H; idx += 256) {
        int h = idx >> 7, d = idx & 127;
        qf[qfb + h*D_QK + d] = qC[(long long)bs*(N_HEADS*D_H) + idx];
    }
    // rope(qR) -> q_full[128:192]
    for (int idx = tid; idx < N_HEADS*(D_R/2); idx += 256) {
        int h = idx >> 5, i = idx & 31;
        float a = qR[(long long)bs*(N_HEADS*D_R) + h*D_R + 2*i];
        float b = qR[(long long)bs*(N_HEADS*D_R) + h*D_R + 2*i + 1];
        float c  = freqs[(long long)s*D_R + 2*i];
        float sn = freqs[(long long)s*D_R + 2*i + 1];
        qf[qfb + h*D_QK + D_H + 2*i]     = a*c - b*sn;
        qf[qfb + h*D_QK + D_H + 2*i + 1] = a*sn + b*c;
    }
    // kR broadcast -> k_full[0:64]
    for (int idx = tid; idx < N_HEADS*D_R; idx += 256) {
        int h = idx >> 6, d = idx & 63;
        kf[qfb + h*D_QK + d] = krs[d];
    }
    // kC -> k_full[64:192]
    for (int idx = tid; idx < N_HEADS*D_H; idx += 256) {
        int h = idx >> 7, d = idx & 127;
        kf[qfb + h*D_QK + D_R + d] = kC[(long long)bs*(N_HEADS*D_H) + idx];
    }
}

// ---------------- causal scaled softmax, in place on w ----------------
// one block per row (b,h,q); row length SEQ=2048, 256 threads, 8 elems/thread
__global__ __launch_bounds__(256)
void softmax_kernel(float* __restrict__ w, float scale)
{
    long long row = blockIdx.x;
    int q = (int)(row & (SEQ - 1));
    float* base = w + row * (long long)SEQ;
    int tid = threadIdx.x;

    float vals[8];
    float mx = -INFINITY;
    #pragma unroll
    for (int it = 0; it < 8; it++) {
        int k = tid + it * 256;
        float v = (k <= q) ? base[k] * scale : -INFINITY;
        vals[it] = v;
        mx = fmaxf(mx, v);
    }
    __shared__ float red[256];
    red[tid] = mx; __syncthreads();
    for (int st = 128; st > 0; st >>= 1) {
        if (tid < st) red[tid] = fmaxf(red[tid], red[tid + st]);
        __syncthreads();
    }
    mx = red[0]; __syncthreads();

    float sum = 0.0f;
    #pragma unroll
    for (int it = 0; it < 8; it++) {
        float e = (vals[it] == -INFINITY) ? 0.0f : __expf(vals[it] - mx);
        vals[it] = e;
        sum += e;
    }
    red[tid] = sum; __syncthreads();
    for (int st = 128; st > 0; st >>= 1) {
        if (tid < st) red[tid] += red[tid + st];
        __syncthreads();
    }
    float inv = 1.0f / red[0];
    #pragma unroll
    for (int it = 0; it < 8; it++) {
        int k = tid + it * 256;
        base[k] = vals[it] * inv;
    }
}

// ---------------- host-side launch ----------------
static float* sym_addr_tmp1()  { void* p; cudaGetSymbolAddress(&p, g_tmp1);  return (float*)p; }
static float* sym_addr_cQ()    { void* p; cudaGetSymbolAddress(&p, g_cQ);    return (float*)p; }
static float* sym_addr_qC()    { void* p; cudaGetSymbolAddress(&p, g_qC);    return (float*)p; }
static float* sym_addr_qR()    { void* p; cudaGetSymbolAddress(&p, g_qR);    return (float*)p; }
static float* sym_addr_kr()    { void* p; cudaGetSymbolAddress(&p, g_kr);    return (float*)p; }
static float* sym_addr_krn()   { void* p; cudaGetSymbolAddress(&p, g_krn);   return (float*)p; }
static float* sym_addr_tmp2()  { void* p; cudaGetSymbolAddress(&p, g_tmp2);  return (float*)p; }
static float* sym_addr_cKV()   { void* p; cudaGetSymbolAddress(&p, g_cKV);   return (float*)p; }
static float* sym_addr_kC()    { void* p; cudaGetSymbolAddress(&p, g_kC);    return (float*)p; }
static float* sym_addr_vC()    { void* p; cudaGetSymbolAddress(&p, g_vC);    return (float*)p; }
static float* sym_addr_qf()    { void* p; cudaGetSymbolAddress(&p, g_qf);    return (float*)p; }
static float* sym_addr_kf()    { void* p; cudaGetSymbolAddress(&p, g_kf);    return (float*)p; }
static float* sym_addr_attn()  { void* p; cudaGetSymbolAddress(&p, g_attn);  return (float*)p; }

static inline void gemm_nn(const float* A, const float* B, const float* bias, float* C,
                           int M, int N, int K, int lda, int ldb, int ldc)
{
    dim3 grid(N/64, M/64, 1);
    gemm_kernel<false><<<grid, 256>>>(A, B, bias, C, M, N, K, lda, ldb, ldc,
                                      0, 0, 0, 0, 0, 0, 1);
}

extern "C" void kernel_launch(void* const* d_in, const int* in_sizes, int n_in,
                              void* d_out, int out_size)
{
    const float* h       = (const float*)d_in[0];
    const float* freqs   = (const float*)d_in[1];
    // d_in[2] = mask (bool) — causal, applied analytically
    const float* Wq_down = (const float*)d_in[3];
    const float* bq_down = (const float*)d_in[4];
    const float* gq_norm = (const float*)d_in[5];
    const float* Wqc     = (const float*)d_in[6];
    const float* bqc     = (const float*)d_in[7];
    const float* Wqr     = (const float*)d_in[8];
    const float* bqr     = (const float*)d_in[9];
    const float* Wkr     = (const float*)d_in[10];
    const float* bkr     = (const float*)d_in[11];
    const float* gkr     = (const float*)d_in[12];
    const float* Wkv     = (const float*)d_in[13];
    const float* bkv     = (const float*)d_in[14];
    const float* gkv     = (const float*)d_in[15];
    const float* Wkc     = (const float*)d_in[16];
    const float* bkc     = (const float*)d_in[17];
    const float* Wvc     = (const float*)d_in[18];
    const float* bvc     = (const float*)d_in[19];
    const float* Wo      = (const float*)d_in[20];
    const float* bo      = (const float*)d_in[21];

    float* out_h = (float*)d_out;
    float* w     = out_h + (long long)NTOK * D_MODEL;   // attention weights output

    float* tmp1 = sym_addr_tmp1();
    float* cQ   = sym_addr_cQ();
    float* qC   = sym_addr_qC();
    float* qR   = sym_addr_qR();
    float* kr   = sym_addr_kr();
    float* krn  = sym_addr_krn();
    float* tmp2 = sym_addr_tmp2();
    float* cKV  = sym_addr_cKV();
    float* kC   = sym_addr_kC();
    float* vC   = sym_addr_vC();
    float* qf   = sym_addr_qf();
    float* kf   = sym_addr_kf();
    float* attn = sym_addr_attn();

    // 1) cQ = rmsnorm(h @ Wq_down + bq_down, gq_norm)
    gemm_nn(h, Wq_down, bq_down, tmp1, NTOK, D_CQ, D_MODEL, D_MODEL, D_CQ, D_CQ);
    rmsnorm_kernel<<<NTOK, 256>>>(tmp1, gq_norm, cQ, D_CQ);

    // 2) qC = cQ @ Wqc + bqc ; qR = cQ @ Wqr + bqr
    gemm_nn(cQ, Wqc, bqc, qC, NTOK, N_HEADS*D_H, D_CQ, D_CQ, N_HEADS*D_H, N_HEADS*D_H);
    gemm_nn(cQ, Wqr, bqr, qR, NTOK, N_HEADS*D_R, D_CQ, D_CQ, N_HEADS*D_R, N_HEADS*D_R);

    // 3) kR = rmsnorm(h @ Wkr + bkr, gkr_norm)
    gemm_nn(h, Wkr, bkr, kr, NTOK, D_R, D_MODEL, D_MODEL, D_R, D_R);
    rmsnorm_kernel<<<NTOK, 256>>>(kr, gkr, krn, D_R);

    // 4) cKV = rmsnorm(h @ Wkv_down + bkv_down, gkv_norm)
    gemm_nn(h, Wkv, bkv, tmp2, NTOK, D_C, D_MODEL, D_MODEL, D_C, D_C);
    rmsnorm_kernel<<<NTOK, 256>>>(tmp2, gkv, cKV, D_C);

    // 5) kC = cKV @ Wkc + bkc ; vC = cKV @ Wvc + bvc
    gemm_nn(cKV, Wkc, bkc, kC, NTOK, N_HEADS*D_H, D_C, D_C, N_HEADS*D_H, N_HEADS*D_H);
    gemm_nn(cKV, Wvc, bvc, vC, NTOK, N_HEADS*D_H, D_C, D_C, N_HEADS*D_H, N_HEADS*D_H);

    // 6) pack q=[qC, rope(qR)], k=[rope(rmsnorm(kR)), kC]   (reference concat order!)
    pack_kernel<<<NTOK, 256>>>(qC, qR, krn, kC, freqs, qf, kf);

    // 7) scores = q @ k^T  per (b,h)  -> w   (batched NT, 64 batches)
    {
        dim3 grid(SEQ/64, SEQ/64, BSZ*N_HEADS);
        long long soQK = (long long)SEQ * N_HEADS * D_QK;    // per-b stride in qf/kf
        long long siQK = D_QK;                                // per-h stride
        long long soW  = (long long)N_HEADS * SEQ * SEQ;      // per-b stride in w
        long long siW  = (long long)SEQ * SEQ;                // per-h stride
        gemm_kernel<true><<<grid, 256>>>(qf, kf, nullptr, w,
                                         SEQ, SEQ, D_QK,
                                         N_HEADS*D_QK, N_HEADS*D_QK, SEQ,
                                         soQK, siQK, soQK, siQK, soW, siW, N_HEADS);
    }

    // 8) causal softmax in place on w
    {
        float scale = 1.0f / sqrtf((float)D_QK);
        softmax_kernel<<<(long long)BSZ * N_HEADS * SEQ, 256>>>(w, scale);
    }

    // 9) attn = w @ vC  per (b,h)  (batched NN, 64 batches)
    {
        dim3 grid(D_H/64, SEQ/64, BSZ*N_HEADS);
        long long soW = (long long)N_HEADS * SEQ * SEQ;
        long long siW = (long long)SEQ * SEQ;
        long long soV = (long long)SEQ * N_HEADS * D_H;
        long long siV = D_H;
        gemm_kernel<false><<<grid, 256>>>(w, vC, nullptr, attn,
                                          SEQ, D_H, SEQ,
                                          SEQ, N_HEADS*D_H, N_HEADS*D_H,
                                          soW, siW, soV, siV, soV, siV, N_HEADS);
    }

    // 10) h_out = attn_flat @ Wo + bo
    gemm_nn(attn, Wo, bo, out_h, NTOK, D_MODEL, N_HEADS*D_H, N_HEADS*D_H, D_MODEL, D_MODEL);
}

// round 3
// speedup vs baseline: 1.4610x; 1.4610x over previous
#include <cuda_runtime.h>
#include <cuda_bf16.h>
#include <math.h>
#include <stdint.h>

// Problem constants
#define D_MODEL 2048
#define N_HEADS 16
#define D_CQ    1536
#define D_C     512
#define D_H     128
#define D_R     64
#define BSZ     4
#define SEQ     2048
#define NTOK    (BSZ*SEQ)            // 8192
#define D_QK    (D_H + D_R)          // 192

#define SW128(o) ((o) ^ (((o) >> 3) & 0x70))

// ---------------- scratch (alloc-free: __device__ globals) ----------------
__device__ float g_tmp1[(long long)NTOK * D_CQ];
__device__ float g_cQ  [(long long)NTOK * D_CQ];
__device__ float g_qC  [(long long)NTOK * (N_HEADS*D_H)];
__device__ float g_qR  [(long long)NTOK * (N_HEADS*D_R)];
__device__ float g_kr  [(long long)NTOK * D_R];
__device__ float g_krn [(long long)NTOK * D_R];
__device__ float g_tmp2[(long long)NTOK * D_C];
__device__ float g_cKV [(long long)NTOK * D_C];
__device__ float g_kC  [(long long)NTOK * (N_HEADS*D_H)];
__device__ float g_vC  [(long long)NTOK * (N_HEADS*D_H)];
__device__ float g_qf  [(long long)NTOK * N_HEADS * D_QK];
__device__ float g_kf  [(long long)NTOK * N_HEADS * D_QK];
__device__ float g_attn[(long long)NTOK * (N_HEADS*D_H)];

// ---------------- helpers ----------------
__device__ __forceinline__ uint32_t smem_u32(const void* p) {
    uint32_t a;
    asm("{ .reg .u64 t; cvta.to.shared.u64 t, %1; cvt.u32.u64 %0, t; }" : "=r"(a) : "l"(p));
    return a;
}

__device__ __forceinline__ void ldsm_x4(uint32_t addr, uint32_t& r0, uint32_t& r1,
                                        uint32_t& r2, uint32_t& r3) {
    asm volatile("ldmatrix.sync.aligned.m8n8.x4.shared.b16 {%0,%1,%2,%3}, [%4];"
                 : "=r"(r0), "=r"(r1), "=r"(r2), "=r"(r3) : "r"(addr));
}

__device__ __forceinline__ void mma_bf16(float* c, uint32_t a0, uint32_t a1,
                                         uint32_t a2, uint32_t a3,
                                         uint32_t b0, uint32_t b1) {
    asm volatile(
        "mma.sync.aligned.m16n8k16.row.col.f32.bf16.bf16.f32 "
        "{%0,%1,%2,%3}, {%4,%5,%6,%7}, {%8,%9}, {%0,%1,%2,%3};"
        : "+f"(c[0]), "+f"(c[1]), "+f"(c[2]), "+f"(c[3])
        : "r"(a0), "r"(a1), "r"(a2), "r"(a3), "r"(b0), "r"(b1));
}

__device__ __forceinline__ void split2(float f0, float f1, uint32_t& hp, uint32_t& lp) {
    __nv_bfloat16 h0 = __float2bfloat16(f0);
    __nv_bfloat16 h1 = __float2bfloat16(f1);
    float l0 = f0 - __bfloat162float(h0);
    float l1 = f1 - __bfloat162float(h1);
    __nv_bfloat16 g0 = __float2bfloat16(l0);
    __nv_bfloat16 g1 = __float2bfloat16(l1);
    hp = ((uint32_t)__bfloat16_as_ushort(h1) << 16) | (uint32_t)__bfloat16_as_ushort(h0);
    lp = ((uint32_t)__bfloat16_as_ushort(g1) << 16) | (uint32_t)__bfloat16_as_ushort(g0);
}

// ---------------- bf16x3 tensor-core GEMM via mma.sync ----------------
// C = A(MxK) * B (+bias).  TB=false: B is KxN; TB=true: B is NxK (C = A*B^T)
// Block 128x128, K-chunk 64. 8 warps: 4 along m (32 rows), 2 along n (64 cols).
// causal_skip: skip tiles fully above diagonal (m,n in same seq index space).
// k_from_m: clip effective K at m0+128 (PV GEMM over causal-zeroed weights).
template<bool TB, bool HB>
__global__ __launch_bounds__(256, 2)
void gemm_mma(const float* __restrict__ A, const float* __restrict__ Bm,
              const float* __restrict__ bias, float* __restrict__ C,
              int M, int N, int K, int lda, int ldb, int ldc,
              long long soA, long long siA, long long soB, long long siB,
              long long soC, long long siC, int IC,
              int causal_skip, int k_from_m)
{
    extern __shared__ char dsm[];
    char* tiles = (char*)(((uintptr_t)dsm + 1023) & ~(uintptr_t)1023);
    char* aHi = tiles;
    char* aLo = tiles + 16384;
    char* bHi = tiles + 32768;
    char* bLo = tiles + 49152;

    int m0 = blockIdx.y * 128;
    int n0 = blockIdx.x * 128;
    if (causal_skip && n0 > m0) return;

    int z = blockIdx.z;
    long long zo = z / IC, zi = z % IC;
    const float* Ab = A  + zo*soA + zi*siA;
    const float* Bb = Bm + zo*soB + zi*siB;
    float*       Cb = C  + zo*soC + zi*siC;

    int Keff = k_from_m ? (m0 + 128 < K ? m0 + 128 : K) : K;

    int tid = threadIdx.x;
    int wid = tid >> 5, lane = tid & 31;
    int wm = (wid & 3) * 32;     // warp m-offset in tile
    int wn = (wid >> 2) * 64;    // warp n-offset in tile

    uint32_t aHiB = smem_u32(aHi), aLoB = smem_u32(aLo);
    uint32_t bHiB = smem_u32(bHi), bLoB = smem_u32(bLo);

    int g = lane >> 3, r = lane & 7;
    // A ldmatrix address components (per x4: mo = 0/16)
    int a_row_off = ((g & 1) << 3) + r;       // +8 for odd groups
    int a_col_off = (g >> 1) << 4;            // +16B for groups 2,3
    // B ldmatrix address components (per x4: no = 0/16/32/48)
    int b_row_off = ((g >> 1) << 3) + r;
    int b_col_off = (g & 1) << 4;

    float acc[2][8][4];
    #pragma unroll
    for (int i = 0; i < 2; i++)
        #pragma unroll
        for (int j = 0; j < 8; j++)
            #pragma unroll
            for (int t = 0; t < 4; t++) acc[i][j][t] = 0.0f;

    const int KT = Keff >> 6;
    for (int kt = 0; kt < KT; kt++) {
        int k0 = kt << 6;

        // ---- load + split A tile [128 m][64 k] ----
        #pragma unroll
        for (int i = 0; i < 8; i++) {
            int f4 = tid + i * 256;
            int rr = f4 >> 4, kq = (f4 & 15) << 2;
            float4 v = *(const float4*)(Ab + (long long)(m0 + rr) * lda + k0 + kq);
            uint32_t off = (uint32_t)(rr * 128 + kq * 2);
            uint32_t h01, l01, h23, l23;
            split2(v.x, v.y, h01, l01);
            split2(v.z, v.w, h23, l23);
            *(uint32_t*)(aHi + SW128(off))     = h01;
            *(uint32_t*)(aHi + SW128(off + 4)) = h23;
            *(uint32_t*)(aLo + SW128(off))     = l01;
            *(uint32_t*)(aLo + SW128(off + 4)) = l23;
        }
        // ---- load + split B tile -> [128 n][64 k] ----
        if (TB) {
            #pragma unroll
            for (int i = 0; i < 8; i++) {
                int f4 = tid + i * 256;
                int rr = f4 >> 4, kq = (f4 & 15) << 2;
                float4 v = *(const float4*)(Bb + (long long)(n0 + rr) * ldb + k0 + kq);
                uint32_t off = (uint32_t)(rr * 128 + kq * 2);
                uint32_t h01, l01, h23, l23;
                split2(v.x, v.y, h01, l01);
                split2(v.z, v.w, h23, l23);
                *(uint32_t*)(bHi + SW128(off))     = h01;
                *(uint32_t*)(bHi + SW128(off + 4)) = h23;
                *(uint32_t*)(bLo + SW128(off))     = l01;
                *(uint32_t*)(bLo + SW128(off + 4)) = l23;
            }
        } else {
            #pragma unroll
            for (int i = 0; i < 8; i++) {
                int f4 = tid + i * 256;
                int kk = f4 >> 5, nq = (f4 & 31) << 2;
                float4 v = *(const float4*)(Bb + (long long)(k0 + kk) * ldb + n0 + nq);
                float vv[4] = {v.x, v.y, v.z, v.w};
                #pragma unroll
                for (int j = 0; j < 4; j++) {
                    uint32_t off = (uint32_t)((nq + j) * 128 + kk * 2);
                    __nv_bfloat16 hb = __float2bfloat16(vv[j]);
                    float lf = vv[j] - __bfloat162float(hb);
                    __nv_bfloat16 lb = __float2bfloat16(lf);
                    *(uint16_t*)(bHi + SW128(off)) = __bfloat16_as_ushort(hb);
                    *(uint16_t*)(bLo + SW128(off)) = __bfloat16_as_ushort(lb);
                }
            }
        }
        __syncthreads();

        // ---- MMA over 4 k-steps of 16 ----
        #pragma unroll
        for (int ks = 0; ks < 4; ks++) {
            int kb = ks << 5;   // byte offset of k-step (16 bf16 = 32B)

            uint32_t ah[2][4], al[2][4];
            #pragma unroll
            for (int mf = 0; mf < 2; mf++) {
                uint32_t off = SW128((uint32_t)((wm + mf*16 + a_row_off) * 128 + kb + a_col_off));
                ldsm_x4(aHiB + off, ah[mf][0], ah[mf][1], ah[mf][2], ah[mf][3]);
                ldsm_x4(aLoB + off, al[mf][0], al[mf][1], al[mf][2], al[mf][3]);
            }

            #pragma unroll
            for (int nh = 0; nh < 2; nh++) {
                uint32_t bh[2][4], bl[2][4];
                #pragma unroll
                for (int q = 0; q < 2; q++) {   // q: 16-col subgroup
                    uint32_t off = SW128((uint32_t)((wn + nh*32 + q*16 + b_row_off) * 128 + kb + b_col_off));
                    ldsm_x4(bHiB + off, bh[q][0], bh[q][1], bh[q][2], bh[q][3]);
                    ldsm_x4(bLoB + off, bl[q][0], bl[q][1], bl[q][2], bl[q][3]);
                }
                #pragma unroll
                for (int mf = 0; mf < 2; mf++) {
                    #pragma unroll
                    for (int nf4 = 0; nf4 < 4; nf4++) {
                        int nf = nh*4 + nf4;
                        int q = nf4 >> 1, hi2 = (nf4 & 1) << 1;
                        uint32_t b0h = bh[q][hi2], b1h = bh[q][hi2+1];
                        uint32_t b0l = bl[q][hi2], b1l = bl[q][hi2+1];
                        float* c = acc[mf][nf];
                        mma_bf16(c, ah[mf][0], ah[mf][1], ah[mf][2], ah[mf][3], b0h, b1h);
                        mma_bf16(c, ah[mf][0], ah[mf][1], ah[mf][2], ah[mf][3], b0l, b1l);
                        mma_bf16(c, al[mf][0], al[mf][1], al[mf][2], al[mf][3], b0h, b1h);
                    }
                }
            }
        }
        __syncthreads();
    }

    // ---- epilogue ----
    #pragma unroll
    for (int mf = 0; mf < 2; mf++) {
        int row = m0 + wm + mf*16 + (lane >> 2);
        #pragma unroll
        for (int nf = 0; nf < 8; nf++) {
            int col = n0 + wn + nf*8 + ((lane & 3) << 1);
            float bx = 0.f, by = 0.f;
            if (HB) { bx = bias[col]; by = bias[col+1]; }
            float2 v0 = make_float2(acc[mf][nf][0] + bx, acc[mf][nf][1] + by);
            float2 v1 = make_float2(acc[mf][nf][2] + bx, acc[mf][nf][3] + by);
            *(float2*)(Cb + (long long)row * ldc + col)       = v0;
            *(float2*)(Cb + (long long)(row + 8) * ldc + col) = v1;
        }
    }
}

// ---------------- scalar SGEMM (small N=64 Wkr GEMM only) ----------------
__global__ __launch_bounds__(256)
void gemm_kernel(const float* __restrict__ A, const float* __restrict__ Bm,
                 const float* __restrict__ bias, float* __restrict__ C,
                 int M, int N, int K, int lda, int ldb, int ldc)
{
    int m0 = blockIdx.y * 64;
    int n0 = blockIdx.x * 64;
    __shared__ float sA[16][68];
    __shared__ float sB[16][68];
    int tid = threadIdx.x;
    int ty = tid >> 4, tx = tid & 15;
    float acc[4][4] = {};
    int arow = tid >> 2;
    int ak   = (tid & 3) * 4;
    int brow = tid >> 4;
    int bcol = (tid & 15) * 4;

    for (int k0 = 0; k0 < K; k0 += 16) {
        float4 a4 = *(const float4*)(A + (long long)(m0 + arow) * lda + k0 + ak);
        sA[ak+0][arow] = a4.x; sA[ak+1][arow] = a4.y;
        sA[ak+2][arow] = a4.z; sA[ak+3][arow] = a4.w;
        float4 b4 = *(const float4*)(Bm + (long long)(k0 + brow) * ldb + n0 + bcol);
        *(float4*)&sB[brow][bcol] = b4;
        __syncthreads();
        #pragma unroll
        for (int kk = 0; kk < 16; kk++) {
            float af[4], bf[4];
            *(float4*)af = *(const float4*)&sA[kk][ty*4];
            *(float4*)bf = *(const float4*)&sB[kk][tx*4];
            #pragma unroll
            for (int i = 0; i < 4; i++)
                #pragma unroll
                for (int j = 0; j < 4; j++)
                    acc[i][j] = fmaf(af[i], bf[j], acc[i][j]);
        }
        __syncthreads();
    }
    #pragma unroll
    for (int i = 0; i < 4; i++) {
        int m = m0 + ty*4 + i;
        #pragma unroll
        for (int j = 0; j < 4; j++) {
            int n = n0 + tx*4 + j;
            float b = bias ? bias[n] : 0.0f;
            C[(long long)m * ldc + n] = acc[i][j] + b;
        }
    }
}

// ---------------- rmsnorm ----------------
__global__ __launch_bounds__(256)
void rmsnorm_kernel(const float* __restrict__ x, const float* __restrict__ g,
                    float* __restrict__ y, int dim)
{
    long long base = (long long)blockIdx.x * dim;
    int tid = threadIdx.x;
    float s = 0.0f;
    for (int i = tid; i < dim; i += 256) {
        float v = x[base + i];
        s += v * v;
    }
    __shared__ float red[256];
    red[tid] = s; __syncthreads();
    for (int st = 128; st > 0; st >>= 1) {
        if (tid < st) red[tid] += red[tid + st];
        __syncthreads();
    }
    float rs = rsqrtf(red[0] / (float)dim + 1e-6f);
    for (int i = tid; i < dim; i += 256)
        y[base + i] = x[base + i] * rs * g[i];
}

// ---------------- pack q_full/k_full with RoPE ----------------
__global__ __launch_bounds__(256)
void pack_kernel(const float* __restrict__ qC, const float* __restrict__ qR,
                 const float* __restrict__ krn, const float* __restrict__ kC,
                 const float* __restrict__ freqs,
                 float* __restrict__ qf, float* __restrict__ kf)
{
    int bs = blockIdx.x;
    int s  = bs & (SEQ - 1);
    long long qfb = (long long)bs * N_HEADS * D_QK;
    int tid = threadIdx.x;

    __shared__ float krs[D_R];
    if (tid < 32) {
        int i = tid;
        float a = krn[(long long)bs*D_R + 2*i];
        float b = krn[(long long)bs*D_R + 2*i + 1];
        float c  = freqs[(long long)s*D_R + 2*i];
        float sn = freqs[(long long)s*D_R + 2*i + 1];
        krs[2*i]   = a*c - b*sn;
        krs[2*i+1] = a*sn + b*c;
    }
    __syncthreads();

    for (int idx = tid; idx < N_HEADS*D_H; idx += 256) {
        int h = idx >> 7, d = idx & 127;
        qf[qfb + h*D_QK + d] = qC[(long long)bs*(N_HEADS*D_H) + idx];
    }
    for (int idx = tid; idx < N_HEADS*(D_R/2); idx += 256) {
        int h = idx >> 5, i = idx & 31;
        float a = qR[(long long)bs*(N_HEADS*D_R) + h*D_R + 2*i];
        float b = qR[(long long)bs*(N_HEADS*D_R) + h*D_R + 2*i + 1];
        float c  = freqs[(long long)s*D_R + 2*i];
        float sn = freqs[(long long)s*D_R + 2*i + 1];
        qf[qfb + h*D_QK + D_H + 2*i]     = a*c - b*sn;
        qf[qfb + h*D_QK + D_H + 2*i + 1] = a*sn + b*c;
    }
    for (int idx = tid; idx < N_HEADS*D_R; idx += 256) {
        int h = idx >> 6, d = idx & 63;
        kf[qfb + h*D_QK + d] = krs[d];
    }
    for (int idx = tid; idx < N_HEADS*D_H; idx += 256) {
        int h = idx >> 7, d = idx & 127;
        kf[qfb + h*D_QK + D_R + d] = kC[(long long)bs*(N_HEADS*D_H) + idx];
    }
}

// ---------------- causal scaled softmax, in place ----------------
__global__ __launch_bounds__(256)
void softmax_kernel(float* __restrict__ w, float scale)
{
    long long row = blockIdx.x;
    int q = (int)(row & (SEQ - 1));
    float* base = w + row * (long long)SEQ;
    int tid = threadIdx.x;

    float vals[8];
    float mx = -INFINITY;
    #pragma unroll
    for (int it = 0; it < 8; it++) {
        int k = tid + it * 256;
        float v = (k <= q) ? base[k] * scale : -INFINITY;
        vals[it] = v;
        mx = fmaxf(mx, v);
    }
    __shared__ float red[256];
    red[tid] = mx; __syncthreads();
    for (int st = 128; st > 0; st >>= 1) {
        if (tid < st) red[tid] = fmaxf(red[tid], red[tid + st]);
        __syncthreads();
    }
    mx = red[0]; __syncthreads();

    float sum = 0.0f;
    #pragma unroll
    for (int it = 0; it < 8; it++) {
        float e = (vals[it] == -INFINITY) ? 0.0f : __expf(vals[it] - mx);
        vals[it] = e;
        sum += e;
    }
    red[tid] = sum; __syncthreads();
    for (int st = 128; st > 0; st >>= 1) {
        if (tid < st) red[tid] += red[tid + st];
        __syncthreads();
    }
    float inv = 1.0f / red[0];
    #pragma unroll
    for (int it = 0; it < 8; it++) {
        int k = tid + it * 256;
        base[k] = vals[it] * inv;
    }
}

// ---------------- host side ----------------
static float* sym_tmp1()  { void* p; cudaGetSymbolAddress(&p, g_tmp1);  return (float*)p; }
static float* sym_cQ()    { void* p; cudaGetSymbolAddress(&p, g_cQ);    return (float*)p; }
static float* sym_qC()    { void* p; cudaGetSymbolAddress(&p, g_qC);    return (float*)p; }
static float* sym_qR()    { void* p; cudaGetSymbolAddress(&p, g_qR);    return (float*)p; }
static float* sym_kr()    { void* p; cudaGetSymbolAddress(&p, g_kr);    return (float*)p; }
static float* sym_krn()   { void* p; cudaGetSymbolAddress(&p, g_krn);   return (float*)p; }
static float* sym_tmp2()  { void* p; cudaGetSymbolAddress(&p, g_tmp2);  return (float*)p; }
static float* sym_cKV()   { void* p; cudaGetSymbolAddress(&p, g_cKV);   return (float*)p; }
static float* sym_kC()    { void* p; cudaGetSymbolAddress(&p, g_kC);    return (float*)p; }
static float* sym_vC()    { void* p; cudaGetSymbolAddress(&p, g_vC);    return (float*)p; }
static float* sym_qf()    { void* p; cudaGetSymbolAddress(&p, g_qf);    return (float*)p; }
static float* sym_kf()    { void* p; cudaGetSymbolAddress(&p, g_kf);    return (float*)p; }
static float* sym_attn()  { void* p; cudaGetSymbolAddress(&p, g_attn);  return (float*)p; }

#define MMA_DSMEM (1024 + 4*16384)

static inline void tc_gemm_nn(const float* A, const float* B, const float* bias, float* C,
                              int M, int N, int K, int lda, int ldb, int ldc)
{
    dim3 grid(N/128, M/128, 1);
    if (bias)
        gemm_mma<false, true><<<grid, 256, MMA_DSMEM>>>(A, B, bias, C, M, N, K, lda, ldb, ldc,
                                                        0,0,0,0,0,0,1, 0,0);
    else
        gemm_mma<false, false><<<grid, 256, MMA_DSMEM>>>(A, B, nullptr, C, M, N, K, lda, ldb, ldc,
                                                         0,0,0,0,0,0,1, 0,0);
}

extern "C" void kernel_launch(void* const* d_in, const int* in_sizes, int n_in,
                              void* d_out, int out_size)
{
    (void)in_sizes; (void)n_in; (void)out_size;
    const float* h       = (const float*)d_in[0];
    const float* freqs   = (const float*)d_in[1];
    const float* Wq_down = (const float*)d_in[3];
    const float* bq_down = (const float*)d_in[4];
    const float* gq_norm = (const float*)d_in[5];
    const float* Wqc     = (const float*)d_in[6];
    const float* bqc     = (const float*)d_in[7];
    const float* Wqr     = (const float*)d_in[8];
    const float* bqr     = (const float*)d_in[9];
    const float* Wkr     = (const float*)d_in[10];
    const float* bkr     = (const float*)d_in[11];
    const float* gkr     = (const float*)d_in[12];
    const float* Wkv     = (const float*)d_in[13];
    const float* bkv     = (const float*)d_in[14];
    const float* gkv     = (const float*)d_in[15];
    const float* Wkc     = (const float*)d_in[16];
    const float* bkc     = (const float*)d_in[17];
    const float* Wvc     = (const float*)d_in[18];
    const float* bvc     = (const float*)d_in[19];
    const float* Wo      = (const float*)d_in[20];
    const float* bo      = (const float*)d_in[21];

    float* out_h = (float*)d_out;
    float* w     = out_h + (long long)NTOK * D_MODEL;

    float* tmp1 = sym_tmp1();
    float* cQ   = sym_cQ();
    float* qC   = sym_qC();
    float* qR   = sym_qR();
    float* kr   = sym_kr();
    float* krn  = sym_krn();
    float* tmp2 = sym_tmp2();
    float* cKV  = sym_cKV();
    float* kC   = sym_kC();
    float* vC   = sym_vC();
    float* qf   = sym_qf();
    float* kf   = sym_kf();
    float* attn = sym_attn();

    cudaFuncSetAttribute(gemm_mma<false, true>,  cudaFuncAttributeMaxDynamicSharedMemorySize, MMA_DSMEM);
    cudaFuncSetAttribute(gemm_mma<false, false>, cudaFuncAttributeMaxDynamicSharedMemorySize, MMA_DSMEM);
    cudaFuncSetAttribute(gemm_mma<true,  false>, cudaFuncAttributeMaxDynamicSharedMemorySize, MMA_DSMEM);

    // 1) cQ = rmsnorm(h @ Wq_down + bq_down)
    tc_gemm_nn(h, Wq_down, bq_down, tmp1, NTOK, D_CQ, D_MODEL, D_MODEL, D_CQ, D_CQ);
    rmsnorm_kernel<<<NTOK, 256>>>(tmp1, gq_norm, cQ, D_CQ);

    // 2) qC, qR
    tc_gemm_nn(cQ, Wqc, bqc, qC, NTOK, N_HEADS*D_H, D_CQ, D_CQ, N_HEADS*D_H, N_HEADS*D_H);
    tc_gemm_nn(cQ, Wqr, bqr, qR, NTOK, N_HEADS*D_R, D_CQ, D_CQ, N_HEADS*D_R, N_HEADS*D_R);

    // 3) kR (N=64 -> scalar path)
    {
        dim3 grid(1, NTOK/64);
        gemm_kernel<<<grid, 256>>>(h, Wkr, bkr, kr, NTOK, D_R, D_MODEL, D_MODEL, D_R, D_R);
    }
    rmsnorm_kernel<<<NTOK, 256>>>(kr, gkr, krn, D_R);

    // 4) cKV
    tc_gemm_nn(h, Wkv, bkv, tmp2, NTOK, D_C, D_MODEL, D_MODEL, D_C, D_C);
    rmsnorm_kernel<<<NTOK, 256>>>(tmp2, gkv, cKV, D_C);

    // 5) kC, vC
    tc_gemm_nn(cKV, Wkc, bkc, kC, NTOK, N_HEADS*D_H, D_C, D_C, N_HEADS*D_H, N_HEADS*D_H);
    tc_gemm_nn(cKV, Wvc, bvc, vC, NTOK, N_HEADS*D_H, D_C, D_C, N_HEADS*D_H, N_HEADS*D_H);

    // 6) pack
    pack_kernel<<<NTOK, 256>>>(qC, qR, krn, kC, freqs, qf, kf);

    // 7) scores = q @ k^T per (b,h), lower-triangle tiles only
    {
        dim3 grid(SEQ/128, SEQ/128, BSZ*N_HEADS);
        long long soQK = (long long)SEQ * N_HEADS * D_QK;
        long long siQK = D_QK;
        long long soW  = (long long)N_HEADS * SEQ * SEQ;
        long long siW  = (long long)SEQ * SEQ;
        gemm_mma<true, false><<<grid, 256, MMA_DSMEM>>>(qf, kf, nullptr, w,
            SEQ, SEQ, D_QK, N_HEADS*D_QK, N_HEADS*D_QK, SEQ,
            soQK, siQK, soQK, siQK, soW, siW, N_HEADS, /*causal_skip=*/1, 0);
    }

    // 8) softmax (writes zeros above the diagonal)
    softmax_kernel<<<(long long)BSZ * N_HEADS * SEQ, 256>>>(w, 1.0f / sqrtf((float)D_QK));

    // 9) attn = w @ vC per (b,h), K clipped at diagonal
    {
        dim3 grid(1, SEQ/128, BSZ*N_HEADS);
        long long soW = (long long)N_HEADS * SEQ * SEQ;
        long long siW = (long long)SEQ * SEQ;
        long long soV = (long long)SEQ * N_HEADS * D_H;
        long long siV = D_H;
        gemm_mma<false, false><<<grid, 256, MMA_DSMEM>>>(w, vC, nullptr, attn,
            SEQ, D_H, SEQ, SEQ, N_HEADS*D_H, N_HEADS*D_H,
            soW, siW, soV, siV, soV, siV, N_HEADS, 0, /*k_from_m=*/1);
    }

    // 10) h_out = attn @ Wo + bo
    tc_gemm_nn(attn, Wo, bo, out_h, NTOK, D_MODEL, N_HEADS*D_H, N_HEADS*D_H, D_MODEL, D_MODEL);
}

// round 4
// speedup vs baseline: 3.4098x; 2.3339x over previous
#include <cuda_runtime.h>
#include <cuda_bf16.h>
#include <math.h>
#include <stdint.h>

#define D_MODEL 2048
#define N_HEADS 16
#define D_CQ    1536
#define D_C     512
#define D_H     128
#define D_R     64
#define BSZ     4
#define SEQ     2048
#define NTOK    (BSZ*SEQ)
#define D_QK    (D_H + D_R)
#define LL long long

#define SW128(o) ((o) ^ (((o) >> 3) & 0x70))

typedef __nv_bfloat16 bf16;

// ---------------- scratch (__device__ globals; alloc-free) ----------------
// fp32 intermediates
__device__ float g_tmp1[(LL)NTOK * D_CQ];
__device__ float g_tmp2[(LL)NTOK * D_C];
__device__ float g_qC  [(LL)NTOK * (N_HEADS*D_H)];
__device__ float g_qR  [(LL)NTOK * (N_HEADS*D_R)];
__device__ float g_kr  [(LL)NTOK * D_R];
__device__ float g_krn [(LL)NTOK * D_R];
__device__ float g_kC  [(LL)NTOK * (N_HEADS*D_H)];
__device__ float g_vC  [(LL)NTOK * (N_HEADS*D_H)];
// bf16 hi/lo split operands
__device__ bf16 g_h_hi[(LL)NTOK * D_MODEL],        g_h_lo[(LL)NTOK * D_MODEL];
__device__ bf16 g_WqdT_hi[(LL)D_CQ * D_MODEL],     g_WqdT_lo[(LL)D_CQ * D_MODEL];     // [1536][2048]
__device__ bf16 g_WqcT_hi[(LL)2048 * D_CQ],        g_WqcT_lo[(LL)2048 * D_CQ];        // [2048][1536]
__device__ bf16 g_WqrT_hi[(LL)1024 * D_CQ],        g_WqrT_lo[(LL)1024 * D_CQ];        // [1024][1536]
__device__ bf16 g_WkvT_hi[(LL)D_C * D_MODEL],      g_WkvT_lo[(LL)D_C * D_MODEL];      // [512][2048]
__device__ bf16 g_WkcT_hi[(LL)2048 * D_C],         g_WkcT_lo[(LL)2048 * D_C];         // [2048][512]
__device__ bf16 g_WvcT_hi[(LL)2048 * D_C],         g_WvcT_lo[(LL)2048 * D_C];
__device__ bf16 g_WoT_hi[(LL)2048 * 2048],         g_WoT_lo[(LL)2048 * 2048];
__device__ bf16 g_cQ_hi[(LL)NTOK * D_CQ],          g_cQ_lo[(LL)NTOK * D_CQ];
__device__ bf16 g_cKV_hi[(LL)NTOK * D_C],          g_cKV_lo[(LL)NTOK * D_C];
__device__ bf16 g_qf_hi[(LL)NTOK * N_HEADS*D_QK],  g_qf_lo[(LL)NTOK * N_HEADS*D_QK];
__device__ bf16 g_kf_hi[(LL)NTOK * N_HEADS*D_QK],  g_kf_lo[(LL)NTOK * N_HEADS*D_QK];
__device__ bf16 g_vCT_hi[(LL)2048 * NTOK],         g_vCT_lo[(LL)2048 * NTOK];         // [2048][8192]
__device__ bf16 g_w_hi[(LL)BSZ*N_HEADS*SEQ*SEQ],   g_w_lo[(LL)BSZ*N_HEADS*SEQ*SEQ];
__device__ bf16 g_attn_hi[(LL)NTOK * 2048],        g_attn_lo[(LL)NTOK * 2048];

// ---------------- device helpers ----------------
__device__ __forceinline__ uint32_t smem_u32(const void* p) {
    uint32_t a;
    asm("{ .reg .u64 t; cvta.to.shared.u64 t, %1; cvt.u32.u64 %0, t; }" : "=r"(a) : "l"(p));
    return a;
}
#define CP16(d, s) asm volatile("cp.async.cg.shared.global [%0], [%1], 16;" :: "r"(d), "l"(s))
#define CP_COMMIT() asm volatile("cp.async.commit_group;" ::: "memory")
#define CP_WAIT1() asm volatile("cp.async.wait_group 1;" ::: "memory")
#define CP_WAIT0() asm volatile("cp.async.wait_group 0;" ::: "memory")

__device__ __forceinline__ void ldsm_x4(uint32_t addr, uint32_t& r0, uint32_t& r1,
                                        uint32_t& r2, uint32_t& r3) {
    asm volatile("ldmatrix.sync.aligned.m8n8.x4.shared.b16 {%0,%1,%2,%3}, [%4];"
                 : "=r"(r0), "=r"(r1), "=r"(r2), "=r"(r3) : "r"(addr));
}
__device__ __forceinline__ void mma_bf16(float* c, const uint32_t* a,
                                         uint32_t b0, uint32_t b1) {
    asm volatile(
        "mma.sync.aligned.m16n8k16.row.col.f32.bf16.bf16.f32 "
        "{%0,%1,%2,%3}, {%4,%5,%6,%7}, {%8,%9}, {%0,%1,%2,%3};"
        : "+f"(c[0]), "+f"(c[1]), "+f"(c[2]), "+f"(c[3])
        : "r"(a[0]), "r"(a[1]), "r"(a[2]), "r"(a[3]), "r"(b0), "r"(b1));
}
__device__ __forceinline__ void splitw(float v, bf16& hi, bf16& lo) {
    hi = __float2bfloat16(v);
    lo = __float2bfloat16(v - __bfloat162float(hi));
}

// ---------------- pipelined bf16x3 GEMM ----------------
// C[M,N] = A * B^T(pre-transposed)  where A splits are [m][k] row-major (lda),
// B splits are [n][k] row-major (ldb). CTA tile 256x128, BK=64, 2-stage cp.async.
// EPI: 0 = fp32 + bias, 1 = fp32, 2 = bf16 hi/lo splits.
template<int EPI>
__global__ __launch_bounds__(256, 1)
void gemm_cp(const bf16* __restrict__ Ahi, const bf16* __restrict__ Alo,
             const bf16* __restrict__ Bhi, const bf16* __restrict__ Blo,
             const float* __restrict__ bias,
             float* __restrict__ C, bf16* __restrict__ Chi, bf16* __restrict__ Clo,
             int K, int lda, int ldb, int ldc,
             LL soA, LL siA, LL soB, LL siB, LL soC, LL siC, int IC,
             int causal, int kclip)
{
    int m0 = blockIdx.y * 256;
    int n0 = blockIdx.x * 128;
    if (causal && n0 >= m0 + 256) return;

    int z = blockIdx.z;
    LL zo = z / IC, zi = z % IC;
    const bf16* Ah_b = Ahi + zo*soA + zi*siA;
    const bf16* Al_b = Alo + zo*soA + zi*siA;
    const bf16* Bh_b = Bhi + zo*soB + zi*siB;
    const bf16* Bl_b = Blo + zo*soB + zi*siB;

    int Keff = kclip ? (m0 + 256 < K ? m0 + 256 : K) : K;
    int KT = Keff >> 6;

    extern __shared__ char sm[];
    uint32_t sb = smem_u32(sm);

    int tid = threadIdx.x;
    int wid = tid >> 5, lane = tid & 31;
    int wm = (wid & 3) << 6;
    int wn = (wid >> 2) << 6;
    int g = lane >> 3, r = lane & 7;
    int aro = ((g & 1) << 3) + r, aco = (g >> 1) << 4;
    int bro = ((g >> 1) << 3) + r, bco = (g & 1) << 4;

    float acc[4][8][4];
    #pragma unroll
    for (int i = 0; i < 4; i++)
        #pragma unroll
        for (int j = 0; j < 8; j++)
            #pragma unroll
            for (int t = 0; t < 4; t++) acc[i][j][t] = 0.0f;

    // stage layout: A_hi 32K | A_lo 32K | B_hi 16K | B_lo 16K = 96K
    #define LOAD_STAGE(s, k0) do {                                             \
        uint32_t st = sb + (uint32_t)(s) * 98304u;                             \
        _Pragma("unroll")                                                      \
        for (int i = 0; i < 8; i++) {                                          \
            int idx = tid + (i << 8);                                          \
            int row = idx >> 3, c = idx & 7;                                   \
            uint32_t d = st + SW128((uint32_t)((row << 7) + (c << 4)));        \
            LL go = (LL)(m0 + row) * lda + (k0) + (c << 3);                    \
            CP16(d,          Ah_b + go);                                       \
            CP16(d + 32768u, Al_b + go);                                       \
        }                                                                      \
        _Pragma("unroll")                                                      \
        for (int i = 0; i < 4; i++) {                                          \
            int idx = tid + (i << 8);                                          \
            int row = idx >> 3, c = idx & 7;                                   \
            uint32_t d = st + 65536u + SW128((uint32_t)((row << 7) + (c << 4)));\
            LL go = (LL)(n0 + row) * ldb + (k0) + (c << 3);                    \
            CP16(d,          Bh_b + go);                                       \
            CP16(d + 16384u, Bl_b + go);                                       \
        }                                                                      \
    } while (0)

    LOAD_STAGE(0, 0);
    CP_COMMIT();

    for (int kt = 0; kt < KT; kt++) {
        if (kt + 1 < KT) {
            LOAD_STAGE((kt + 1) & 1, (kt + 1) << 6);
            CP_COMMIT();
            CP_WAIT1();
        } else {
            CP_WAIT0();
        }
        __syncthreads();

        uint32_t aB = sb + (uint32_t)(kt & 1) * 98304u;
        uint32_t bB = aB + 65536u;

        #pragma unroll
        for (int ks = 0; ks < 4; ks++) {
            int kb = ks << 5;
            uint32_t ah[4][4], al[4][4];
            #pragma unroll
            for (int mf = 0; mf < 4; mf++) {
                uint32_t off = SW128((uint32_t)((wm + (mf << 4) + aro) * 128 + kb + aco));
                ldsm_x4(aB + off,          ah[mf][0], ah[mf][1], ah[mf][2], ah[mf][3]);
                ldsm_x4(aB + 32768u + off, al[mf][0], al[mf][1], al[mf][2], al[mf][3]);
            }
            #pragma unroll
            for (int ng = 0; ng < 4; ng++) {
                uint32_t off = SW128((uint32_t)((wn + (ng << 4) + bro) * 128 + kb + bco));
                uint32_t bh0, bh1, bh2, bh3, bl0, bl1, bl2, bl3;
                ldsm_x4(bB + off,          bh0, bh1, bh2, bh3);
                ldsm_x4(bB + 16384u + off, bl0, bl1, bl2, bl3);
                #pragma unroll
                for (int mf = 0; mf < 4; mf++) {
                    float* c0 = acc[mf][(ng << 1)];
                    float* c1 = acc[mf][(ng << 1) + 1];
                    mma_bf16(c0, ah[mf], bh0, bh1);
                    mma_bf16(c1, ah[mf], bh2, bh3);
                    mma_bf16(c0, ah[mf], bl0, bl1);
                    mma_bf16(c1, ah[mf], bl2, bl3);
                    mma_bf16(c0, al[mf], bh0, bh1);
                    mma_bf16(c1, al[mf], bh2, bh3);
                }
            }
        }
        __syncthreads();
    }

    // epilogue
    #pragma unroll
    for (int mf = 0; mf < 4; mf++) {
        int row = m0 + wm + (mf << 4) + (lane >> 2);
        #pragma unroll
        for (int nf = 0; nf < 8; nf++) {
            int col = n0 + wn + (nf << 3) + ((lane & 3) << 1);
            float* a = acc[mf][nf];
            if (EPI == 0) {
                float bx = bias[col], by = bias[col + 1];
                float* Cb = C + zo*soC + zi*siC;
                *(float2*)(Cb + (LL)row * ldc + col)       = make_float2(a[0] + bx, a[1] + by);
                *(float2*)(Cb + (LL)(row + 8) * ldc + col) = make_float2(a[2] + bx, a[3] + by);
            } else if (EPI == 1) {
                float* Cb = C + zo*soC + zi*siC;
                *(float2*)(Cb + (LL)row * ldc + col)       = make_float2(a[0], a[1]);
                *(float2*)(Cb + (LL)(row + 8) * ldc + col) = make_float2(a[2], a[3]);
            } else {
                bf16* Hb = Chi + zo*soC + zi*siC;
                bf16* Lb = Clo + zo*soC + zi*siC;
                bf16 h0, l0, h1, l1;
                splitw(a[0], h0, l0); splitw(a[1], h1, l1);
                uint32_t hp = ((uint32_t)__bfloat16_as_ushort(h1) << 16) | __bfloat16_as_ushort(h0);
                uint32_t lp = ((uint32_t)__bfloat16_as_ushort(l1) << 16) | __bfloat16_as_ushort(l0);
                *(uint32_t*)(Hb + (LL)row * ldc + col) = hp;
                *(uint32_t*)(Lb + (LL)row * ldc + col) = lp;
                splitw(a[2], h0, l0); splitw(a[3], h1, l1);
                hp = ((uint32_t)__bfloat16_as_ushort(h1) << 16) | __bfloat16_as_ushort(h0);
                lp = ((uint32_t)__bfloat16_as_ushort(l1) << 16) | __bfloat16_as_ushort(l0);
                *(uint32_t*)(Hb + (LL)(row + 8) * ldc + col) = hp;
                *(uint32_t*)(Lb + (LL)(row + 8) * ldc + col) = lp;
            }
        }
    }
}

// ---------------- split kernels ----------------
__global__ __launch_bounds__(256)
void split_rm(const float* __restrict__ x, bf16* __restrict__ hi, bf16* __restrict__ lo)
{
    LL base = ((LL)blockIdx.x * 256 + threadIdx.x) * 4;
    float4 v = *(const float4*)(x + base);
    bf16 h[4], l[4];
    splitw(v.x, h[0], l[0]); splitw(v.y, h[1], l[1]);
    splitw(v.z, h[2], l[2]); splitw(v.w, h[3], l[3]);
    *(uint2*)(hi + base) = *(uint2*)h;
    *(uint2*)(lo + base) = *(uint2*)l;
}

// [R][C] fp32 -> [C][R] bf16 hi/lo
__global__ __launch_bounds__(256)
void split_tr(const float* __restrict__ x, bf16* __restrict__ hi, bf16* __restrict__ lo,
              int R, int C)
{
    __shared__ float s[32][33];
    int tx = threadIdx.x & 31, ty = threadIdx.x >> 5;
    int r0 = blockIdx.y * 32, c0 = blockIdx.x * 32;
    #pragma unroll
    for (int j = 0; j < 4; j++)
        s[ty + 8*j][tx] = x[(LL)(r0 + ty + 8*j) * C + c0 + tx];
    __syncthreads();
    #pragma unroll
    for (int j = 0; j < 4; j++) {
        float v = s[tx][ty + 8*j];
        bf16 h, l; splitw(v, h, l);
        LL o = (LL)(c0 + ty + 8*j) * R + r0 + tx;
        hi[o] = h; lo[o] = l;
    }
}

// ---------------- rmsnorm ----------------
__global__ __launch_bounds__(256)
void rmsnorm_kernel(const float* __restrict__ x, const float* __restrict__ g,
                    float* __restrict__ y, int dim)
{
    LL base = (LL)blockIdx.x * dim;
    int tid = threadIdx.x;
    float s = 0.0f;
    for (int i = tid; i < dim; i += 256) { float v = x[base + i]; s += v * v; }
    __shared__ float red[256];
    red[tid] = s; __syncthreads();
    for (int st = 128; st > 0; st >>= 1) {
        if (tid < st) red[tid] += red[tid + st];
        __syncthreads();
    }
    float rs = rsqrtf(red[0] / (float)dim + 1e-6f);
    for (int i = tid; i < dim; i += 256)
        y[base + i] = x[base + i] * rs * g[i];
}

__global__ __launch_bounds__(256)
void rmsnorm_split(const float* __restrict__ x, const float* __restrict__ g,
                   bf16* __restrict__ yh, bf16* __restrict__ yl, int dim)
{
    LL base = (LL)blockIdx.x * dim;
    int tid = threadIdx.x;
    float s = 0.0f;
    for (int i = tid; i < dim; i += 256) { float v = x[base + i]; s += v * v; }
    __shared__ float red[256];
    red[tid] = s; __syncthreads();
    for (int st = 128; st > 0; st >>= 1) {
        if (tid < st) red[tid] += red[tid + st];
        __syncthreads();
    }
    float rs = rsqrtf(red[0] / (float)dim + 1e-6f);
    for (int i = tid; i < dim; i += 256) {
        float v = x[base + i] * rs * g[i];
        bf16 h, l; splitw(v, h, l);
        yh[base + i] = h; yl[base + i] = l;
    }
}

// ---------------- pack with RoPE -> bf16 splits ----------------
__global__ __launch_bounds__(256)
void pack_split(const float* __restrict__ qC, const float* __restrict__ qR,
                const float* __restrict__ krn, const float* __restrict__ kC,
                const float* __restrict__ freqs,
                bf16* __restrict__ qfh, bf16* __restrict__ qfl,
                bf16* __restrict__ kfh, bf16* __restrict__ kfl)
{
    int bs = blockIdx.x;
    int s  = bs & (SEQ - 1);
    LL qfb = (LL)bs * N_HEADS * D_QK;
    int tid = threadIdx.x;

    __shared__ float krs[D_R];
    if (tid < 32) {
        int i = tid;
        float a = krn[(LL)bs*D_R + 2*i];
        float b = krn[(LL)bs*D_R + 2*i + 1];
        float c  = freqs[(LL)s*D_R + 2*i];
        float sn = freqs[(LL)s*D_R + 2*i + 1];
        krs[2*i]   = a*c - b*sn;
        krs[2*i+1] = a*sn + b*c;
    }
    __syncthreads();

    for (int idx = tid; idx < N_HEADS*D_H; idx += 256) {
        int h = idx >> 7, d = idx & 127;
        float v = qC[(LL)bs*(N_HEADS*D_H) + idx];
        bf16 hh, ll; splitw(v, hh, ll);
        qfh[qfb + h*D_QK + d] = hh; qfl[qfb + h*D_QK + d] = ll;
    }
    for (int idx = tid; idx < N_HEADS*(D_R/2); idx += 256) {
        int h = idx >> 5, i = idx & 31;
        float a = qR[(LL)bs*(N_HEADS*D_R) + h*D_R + 2*i];
        float b = qR[(LL)bs*(N_HEADS*D_R) + h*D_R + 2*i + 1];
        float c  = freqs[(LL)s*D_R + 2*i];
        float sn = freqs[(LL)s*D_R + 2*i + 1];
        float v0 = a*c - b*sn, v1 = a*sn + b*c;
        bf16 hh, ll;
        splitw(v0, hh, ll);
        qfh[qfb + h*D_QK + D_H + 2*i] = hh;   qfl[qfb + h*D_QK + D_H + 2*i] = ll;
        splitw(v1, hh, ll);
        qfh[qfb + h*D_QK + D_H + 2*i+1] = hh; qfl[qfb + h*D_QK + D_H + 2*i+1] = ll;
    }
    for (int idx = tid; idx < N_HEADS*D_R; idx += 256) {
        int h = idx >> 6, d = idx & 63;
        bf16 hh, ll; splitw(krs[d], hh, ll);
        kfh[qfb + h*D_QK + d] = hh; kfl[qfb + h*D_QK + d] = ll;
    }
    for (int idx = tid; idx < N_HEADS*D_H; idx += 256) {
        int h = idx >> 7, d = idx & 127;
        float v = kC[(LL)bs*(N_HEADS*D_H) + idx];
        bf16 hh, ll; splitw(v, hh, ll);
        kfh[qfb + h*D_QK + D_R + d] = hh; kfl[qfb + h*D_QK + D_R + d] = ll;
    }
}

// ---------------- causal softmax + split emission ----------------
__global__ __launch_bounds__(256)
void softmax_kernel(float* __restrict__ w, bf16* __restrict__ wh, bf16* __restrict__ wl,
                    float scale)
{
    LL row = blockIdx.x;
    int q = (int)(row & (SEQ - 1));
    float* base = w + row * (LL)SEQ;
    bf16* bh = wh + row * (LL)SEQ;
    bf16* bl = wl + row * (LL)SEQ;
    int tid = threadIdx.x;

    float vals[8];
    float mx = -INFINITY;
    #pragma unroll
    for (int it = 0; it < 8; it++) {
        int k = tid + it * 256;
        float v = (k <= q) ? base[k] * scale : -INFINITY;
        vals[it] = v;
        mx = fmaxf(mx, v);
    }
    __shared__ float red[256];
    red[tid] = mx; __syncthreads();
    for (int st = 128; st > 0; st >>= 1) {
        if (tid < st) red[tid] = fmaxf(red[tid], red[tid + st]);
        __syncthreads();
    }
    mx = red[0]; __syncthreads();

    float sum = 0.0f;
    #pragma unroll
    for (int it = 0; it < 8; it++) {
        float e = (vals[it] == -INFINITY) ? 0.0f : __expf(vals[it] - mx);
        vals[it] = e;
        sum += e;
    }
    red[tid] = sum; __syncthreads();
    for (int st = 128; st > 0; st >>= 1) {
        if (tid < st) red[tid] += red[tid + st];
        __syncthreads();
    }
    float inv = 1.0f / red[0];

    int kLim = ((q >> 8) + 1) << 8;   // exactly what PV's K-clip reads
    #pragma unroll
    for (int it = 0; it < 8; it++) {
        int k = tid + it * 256;
        float p = vals[it] * inv;
        base[k] = p;
        if (k < kLim) {
            bf16 h, l; splitw(p, h, l);
            bh[k] = h; bl[k] = l;
        }
    }
}

// ---------------- scalar SGEMM for the tiny N=64 kr projection ----------------
__global__ __launch_bounds__(256)
void gemm_small(const float* __restrict__ A, const float* __restrict__ Bm,
                const float* __restrict__ bias, float* __restrict__ C,
                int K, int lda, int ldb, int ldc)
{
    int m0 = blockIdx.y * 64;
    int n0 = blockIdx.x * 64;
    __shared__ float sA[16][68];
    __shared__ float sB[16][68];
    int tid = threadIdx.x;
    int ty = tid >> 4, tx = tid & 15;
    float acc[4][4] = {};
    int arow = tid >> 2, ak = (tid & 3) * 4;
    int brow = tid >> 4, bcol = (tid & 15) * 4;

    for (int k0 = 0; k0 < K; k0 += 16) {
        float4 a4 = *(const float4*)(A + (LL)(m0 + arow) * lda + k0 + ak);
        sA[ak+0][arow] = a4.x; sA[ak+1][arow] = a4.y;
        sA[ak+2][arow] = a4.z; sA[ak+3][arow] = a4.w;
        float4 b4 = *(const float4*)(Bm + (LL)(k0 + brow) * ldb + n0 + bcol);
        *(float4*)&sB[brow][bcol] = b4;
        __syncthreads();
        #pragma unroll
        for (int kk = 0; kk < 16; kk++) {
            float af[4], bf[4];
            *(float4*)af = *(const float4*)&sA[kk][ty*4];
            *(float4*)bf = *(const float4*)&sB[kk][tx*4];
            #pragma unroll
            for (int i = 0; i < 4; i++)
                #pragma unroll
                for (int j = 0; j < 4; j++)
                    acc[i][j] = fmaf(af[i], bf[j], acc[i][j]);
        }
        __syncthreads();
    }
    #pragma unroll
    for (int i = 0; i < 4; i++)
        #pragma unroll
        for (int j = 0; j < 4; j++)
            C[(LL)(m0 + ty*4 + i) * ldc + n0 + tx*4 + j] = acc[i][j] + bias[n0 + tx*4 + j];
}

// ---------------- host ----------------
#define SYMF(name) ({ void* p_; cudaGetSymbolAddress(&p_, name); (float*)p_; })
#define SYMB(name) ({ void* p_; cudaGetSymbolAddress(&p_, name); (bf16*)p_; })

#define GEMM_SMEM 196608

extern "C" void kernel_launch(void* const* d_in, const int* in_sizes, int n_in,
                              void* d_out, int out_size)
{
    (void)in_sizes; (void)n_in; (void)out_size;
    const float* h       = (const float*)d_in[0];
    const float* freqs   = (const float*)d_in[1];
    const float* Wq_down = (const float*)d_in[3];
    const float* bq_down = (const float*)d_in[4];
    const float* gq_norm = (const float*)d_in[5];
    const float* Wqc     = (const float*)d_in[6];
    const float* bqc     = (const float*)d_in[7];
    const float* Wqr     = (const float*)d_in[8];
    const float* bqr     = (const float*)d_in[9];
    const float* Wkr     = (const float*)d_in[10];
    const float* bkr     = (const float*)d_in[11];
    const float* gkr     = (const float*)d_in[12];
    const float* Wkv     = (const float*)d_in[13];
    const float* bkv     = (const float*)d_in[14];
    const float* gkv     = (const float*)d_in[15];
    const float* Wkc     = (const float*)d_in[16];
    const float* bkc     = (const float*)d_in[17];
    const float* Wvc     = (const float*)d_in[18];
    const float* bvc     = (const float*)d_in[19];
    const float* Wo      = (const float*)d_in[20];
    const float* bo      = (const float*)d_in[21];

    float* out_h = (float*)d_out;
    float* w     = out_h + (LL)NTOK * D_MODEL;

    float* tmp1 = SYMF(g_tmp1); float* tmp2 = SYMF(g_tmp2);
    float* qC = SYMF(g_qC);     float* qR = SYMF(g_qR);
    float* kr = SYMF(g_kr);     float* krn = SYMF(g_krn);
    float* kC = SYMF(g_kC);     float* vC = SYMF(g_vC);

    bf16 *h_hi = SYMB(g_h_hi), *h_lo = SYMB(g_h_lo);
    bf16 *WqdT_hi = SYMB(g_WqdT_hi), *WqdT_lo = SYMB(g_WqdT_lo);
    bf16 *WqcT_hi = SYMB(g_WqcT_hi), *WqcT_lo = SYMB(g_WqcT_lo);
    bf16 *WqrT_hi = SYMB(g_WqrT_hi), *WqrT_lo = SYMB(g_WqrT_lo);
    bf16 *WkvT_hi = SYMB(g_WkvT_hi), *WkvT_lo = SYMB(g_WkvT_lo);
    bf16 *WkcT_hi = SYMB(g_WkcT_hi), *WkcT_lo = SYMB(g_WkcT_lo);
    bf16 *WvcT_hi = SYMB(g_WvcT_hi), *WvcT_lo = SYMB(g_WvcT_lo);
    bf16 *WoT_hi  = SYMB(g_WoT_hi),  *WoT_lo  = SYMB(g_WoT_lo);
    bf16 *cQ_hi = SYMB(g_cQ_hi), *cQ_lo = SYMB(g_cQ_lo);
    bf16 *cKV_hi = SYMB(g_cKV_hi), *cKV_lo = SYMB(g_cKV_lo);
    bf16 *qf_hi = SYMB(g_qf_hi), *qf_lo = SYMB(g_qf_lo);
    bf16 *kf_hi = SYMB(g_kf_hi), *kf_lo = SYMB(g_kf_lo);
    bf16 *vCT_hi = SYMB(g_vCT_hi), *vCT_lo = SYMB(g_vCT_lo);
    bf16 *w_hi = SYMB(g_w_hi), *w_lo = SYMB(g_w_lo);
    bf16 *attn_hi = SYMB(g_attn_hi), *attn_lo = SYMB(g_attn_lo);

    cudaFuncSetAttribute(gemm_cp<0>, cudaFuncAttributeMaxDynamicSharedMemorySize, GEMM_SMEM);
    cudaFuncSetAttribute(gemm_cp<1>, cudaFuncAttributeMaxDynamicSharedMemorySize, GEMM_SMEM);
    cudaFuncSetAttribute(gemm_cp<2>, cudaFuncAttributeMaxDynamicSharedMemorySize, GEMM_SMEM);

    // -------- operand splits --------
    split_rm<<<(LL)NTOK*D_MODEL/1024, 256>>>(h, h_hi, h_lo);
    split_tr<<<dim3(D_CQ/32, D_MODEL/32), 256>>>(Wq_down, WqdT_hi, WqdT_lo, D_MODEL, D_CQ);
    split_tr<<<dim3(2048/32, D_CQ/32), 256>>>(Wqc, WqcT_hi, WqcT_lo, D_CQ, 2048);
    split_tr<<<dim3(1024/32, D_CQ/32), 256>>>(Wqr, WqrT_hi, WqrT_lo, D_CQ, 1024);
    split_tr<<<dim3(D_C/32, D_MODEL/32), 256>>>(Wkv, WkvT_hi, WkvT_lo, D_MODEL, D_C);
    split_tr<<<dim3(2048/32, D_C/32), 256>>>(Wkc, WkcT_hi, WkcT_lo, D_C, 2048);
    split_tr<<<dim3(2048/32, D_C/32), 256>>>(Wvc, WvcT_hi, WvcT_lo, D_C, 2048);
    split_tr<<<dim3(2048/32, 2048/32), 256>>>(Wo, WoT_hi, WoT_lo, 2048, 2048);

    // -------- 1) cQ = rmsnorm(h @ Wq_down + b) --------
    gemm_cp<0><<<dim3(D_CQ/128, NTOK/256), 256, GEMM_SMEM>>>(
        h_hi, h_lo, WqdT_hi, WqdT_lo, bq_down, tmp1, nullptr, nullptr,
        D_MODEL, D_MODEL, D_MODEL, D_CQ, 0,0,0,0,0,0,1, 0,0);
    rmsnorm_split<<<NTOK, 256>>>(tmp1, gq_norm, cQ_hi, cQ_lo, D_CQ);

    // -------- 2) qC, qR --------
    gemm_cp<0><<<dim3(2048/128, NTOK/256), 256, GEMM_SMEM>>>(
        cQ_hi, cQ_lo, WqcT_hi, WqcT_lo, bqc, qC, nullptr, nullptr,
        D_CQ, D_CQ, D_CQ, 2048, 0,0,0,0,0,0,1, 0,0);
    gemm_cp<0><<<dim3(1024/128, NTOK/256), 256, GEMM_SMEM>>>(
        cQ_hi, cQ_lo, WqrT_hi, WqrT_lo, bqr, qR, nullptr, nullptr,
        D_CQ, D_CQ, D_CQ, 1024, 0,0,0,0,0,0,1, 0,0);

    // -------- 3) kr --------
    gemm_small<<<dim3(1, NTOK/64), 256>>>(h, Wkr, bkr, kr, D_MODEL, D_MODEL, D_R, D_R);
    rmsnorm_kernel<<<NTOK, 256>>>(kr, gkr, krn, D_R);

    // -------- 4) cKV --------
    gemm_cp<0><<<dim3(D_C/128, NTOK/256), 256, GEMM_SMEM>>>(
        h_hi, h_lo, WkvT_hi, WkvT_lo, bkv, tmp2, nullptr, nullptr,
        D_MODEL, D_MODEL, D_MODEL, D_C, 0,0,0,0,0,0,1, 0,0);
    rmsnorm_split<<<NTOK, 256>>>(tmp2, gkv, cKV_hi, cKV_lo, D_C);

    // -------- 5) kC, vC --------
    gemm_cp<0><<<dim3(2048/128, NTOK/256), 256, GEMM_SMEM>>>(
        cKV_hi, cKV_lo, WkcT_hi, WkcT_lo, bkc, kC, nullptr, nullptr,
        D_C, D_C, D_C, 2048, 0,0,0,0,0,0,1, 0,0);
    gemm_cp<0><<<dim3(2048/128, NTOK/256), 256, GEMM_SMEM>>>(
        cKV_hi, cKV_lo, WvcT_hi, WvcT_lo, bvc, vC, nullptr, nullptr,
        D_C, D_C, D_C, 2048, 0,0,0,0,0,0,1, 0,0);
    split_tr<<<dim3(2048/32, NTOK/32), 256>>>(vC, vCT_hi, vCT_lo, NTOK, 2048);

    // -------- 6) pack + RoPE --------
    pack_split<<<NTOK, 256>>>(qC, qR, krn, kC, freqs, qf_hi, qf_lo, kf_hi, kf_lo);

    // -------- 7) scores = q k^T (causal tiles) --------
    {
        LL soQK = (LL)SEQ * N_HEADS * D_QK, siQK = D_QK;
        LL soW  = (LL)N_HEADS * SEQ * SEQ,  siW  = (LL)SEQ * SEQ;
        gemm_cp<1><<<dim3(SEQ/128, SEQ/256, BSZ*N_HEADS), 256, GEMM_SMEM>>>(
            qf_hi, qf_lo, kf_hi, kf_lo, nullptr, w, nullptr, nullptr,
            D_QK, N_HEADS*D_QK, N_HEADS*D_QK, SEQ,
            soQK, siQK, soQK, siQK, soW, siW, N_HEADS, /*causal=*/1, 0);
    }

    // -------- 8) softmax (fp32 w + bf16 splits) --------
    softmax_kernel<<<(LL)BSZ*N_HEADS*SEQ, 256>>>(w, w_hi, w_lo, 1.0f / sqrtf((float)D_QK));

    // -------- 9) attn = w @ vC (K clipped at diagonal), split output --------
    {
        LL soW = (LL)N_HEADS * SEQ * SEQ, siW = (LL)SEQ * SEQ;
        LL soB = 2048;                       // vCT [dim][b*2048+tok]: batch stride
        LL siB = (LL)D_H * NTOK;             // head stride (h*128 rows)
        LL soC = (LL)SEQ * 2048, siC = D_H;  // attn [b*tok][h*128+d]
        gemm_cp<2><<<dim3(D_H/128, SEQ/256, BSZ*N_HEADS), 256, GEMM_SMEM>>>(
            w_hi, w_lo, vCT_hi, vCT_lo, nullptr, nullptr, attn_hi, attn_lo,
            SEQ, SEQ, NTOK, 2048,
            soW, siW, soB, siB, soC, siC, N_HEADS, 0, /*kclip=*/1);
    }

    // -------- 10) h_out = attn @ Wo + bo --------
    gemm_cp<0><<<dim3(2048/128, NTOK/256), 256, GEMM_SMEM>>>(
        attn_hi, attn_lo, WoT_hi, WoT_lo, bo, out_h, nullptr, nullptr,
        2048, 2048, 2048, 2048, 0,0,0,0,0,0,1, 0,0);
}

// round 5
// speedup vs baseline: 3.4335x; 1.0070x over previous
#include <cuda_runtime.h>
#include <cuda_bf16.h>
#include <math.h>
#include <stdint.h>

#define D_MODEL 2048
#define N_HEADS 16
#define D_CQ    1536
#define D_C     512
#define D_H     128
#define D_R     64
#define BSZ     4
#define SEQ     2048
#define NTOK    (BSZ*SEQ)
#define D_QK    (D_H + D_R)
#define LL long long

#define SW128(o) ((o) ^ (((o) >> 3) & 0x70))
#define SW64(o)  ((o) ^ (((o) >> 2) & 0x30))

typedef __nv_bfloat16 bf16;

// ---------------- scratch (__device__ globals; alloc-free) ----------------
__device__ float g_tmp1[(LL)NTOK * D_CQ];
__device__ float g_tmp2[(LL)NTOK * D_C];
__device__ float g_qC  [(LL)NTOK * (N_HEADS*D_H)];
__device__ float g_qR  [(LL)NTOK * (N_HEADS*D_R)];
__device__ float g_kr  [(LL)NTOK * D_R];
__device__ float g_krn [(LL)NTOK * D_R];
__device__ float g_kC  [(LL)NTOK * (N_HEADS*D_H)];
__device__ float g_vC  [(LL)NTOK * (N_HEADS*D_H)];
__device__ bf16 g_h_hi[(LL)NTOK * D_MODEL],        g_h_lo[(LL)NTOK * D_MODEL];
__device__ bf16 g_WqdT_hi[(LL)D_CQ * D_MODEL],     g_WqdT_lo[(LL)D_CQ * D_MODEL];
__device__ bf16 g_WqcT_hi[(LL)2048 * D_CQ],        g_WqcT_lo[(LL)2048 * D_CQ];
__device__ bf16 g_WqrT_hi[(LL)1024 * D_CQ],        g_WqrT_lo[(LL)1024 * D_CQ];
__device__ bf16 g_WkvT_hi[(LL)D_C * D_MODEL],      g_WkvT_lo[(LL)D_C * D_MODEL];
__device__ bf16 g_WkcT_hi[(LL)2048 * D_C],         g_WkcT_lo[(LL)2048 * D_C];
__device__ bf16 g_WvcT_hi[(LL)2048 * D_C],         g_WvcT_lo[(LL)2048 * D_C];
__device__ bf16 g_WoT_hi[(LL)2048 * 2048],         g_WoT_lo[(LL)2048 * 2048];
__device__ bf16 g_cQ_hi[(LL)NTOK * D_CQ],          g_cQ_lo[(LL)NTOK * D_CQ];
__device__ bf16 g_cKV_hi[(LL)NTOK * D_C],          g_cKV_lo[(LL)NTOK * D_C];
__device__ bf16 g_qf_hi[(LL)NTOK * N_HEADS*D_QK],  g_qf_lo[(LL)NTOK * N_HEADS*D_QK];
__device__ bf16 g_kf_hi[(LL)NTOK * N_HEADS*D_QK],  g_kf_lo[(LL)NTOK * N_HEADS*D_QK];
__device__ bf16 g_vCT_hi[(LL)2048 * NTOK],         g_vCT_lo[(LL)2048 * NTOK];
__device__ bf16 g_w_hi[(LL)BSZ*N_HEADS*SEQ*SEQ],   g_w_lo[(LL)BSZ*N_HEADS*SEQ*SEQ];
__device__ bf16 g_attn_hi[(LL)NTOK * 2048],        g_attn_lo[(LL)NTOK * 2048];

// ---------------- device helpers ----------------
__device__ __forceinline__ uint32_t smem_u32(const void* p) {
    uint32_t a;
    asm("{ .reg .u64 t; cvta.to.shared.u64 t, %1; cvt.u32.u64 %0, t; }" : "=r"(a) : "l"(p));
    return a;
}
#define CP16(d, s) asm volatile("cp.async.cg.shared.global [%0], [%1], 16;" :: "r"(d), "l"(s))
#define CP_COMMIT() asm volatile("cp.async.commit_group;" ::: "memory")
#define CP_WAIT1() asm volatile("cp.async.wait_group 1;" ::: "memory")
#define CP_WAIT0() asm volatile("cp.async.wait_group 0;" ::: "memory")

__device__ __forceinline__ void ldsm_x4(uint32_t addr, uint32_t& r0, uint32_t& r1,
                                        uint32_t& r2, uint32_t& r3) {
    asm volatile("ldmatrix.sync.aligned.m8n8.x4.shared.b16 {%0,%1,%2,%3}, [%4];"
                 : "=r"(r0), "=r"(r1), "=r"(r2), "=r"(r3) : "r"(addr));
}
__device__ __forceinline__ void mma_bf16(float* c, const uint32_t* a,
                                         uint32_t b0, uint32_t b1) {
    asm volatile(
        "mma.sync.aligned.m16n8k16.row.col.f32.bf16.bf16.f32 "
        "{%0,%1,%2,%3}, {%4,%5,%6,%7}, {%8,%9}, {%0,%1,%2,%3};"
        : "+f"(c[0]), "+f"(c[1]), "+f"(c[2]), "+f"(c[3])
        : "r"(a[0]), "r"(a[1]), "r"(a[2]), "r"(a[3]), "r"(b0), "r"(b1));
}
__device__ __forceinline__ void splitw(float v, bf16& hi, bf16& lo) {
    hi = __float2bfloat16(v);
    lo = __float2bfloat16(v - __bfloat162float(hi));
}

// ---------------- pipelined bf16x3 GEMM (256x128, BK=64, 2-stage, 1 sync/kt) ----------------
// EPI: 0 = fp32 + bias, 1 = fp32, 2 = bf16 hi/lo splits.
template<int EPI>
__global__ __launch_bounds__(256, 1)
void gemm_cp(const bf16* __restrict__ Ahi, const bf16* __restrict__ Alo,
             const bf16* __restrict__ Bhi, const bf16* __restrict__ Blo,
             const float* __restrict__ bias,
             float* __restrict__ C, bf16* __restrict__ Chi, bf16* __restrict__ Clo,
             int K, int lda, int ldb, int ldc,
             LL soA, LL siA, LL soB, LL siB, LL soC, LL siC, int IC,
             int kclip)
{
    int m0 = blockIdx.y * 256;
    int n0 = blockIdx.x * 128;

    int z = blockIdx.z;
    LL zo = z / IC, zi = z % IC;
    const bf16* Ah_b = Ahi + zo*soA + zi*siA;
    const bf16* Al_b = Alo + zo*soA + zi*siA;
    const bf16* Bh_b = Bhi + zo*soB + zi*siB;
    const bf16* Bl_b = Blo + zo*soB + zi*siB;

    int Keff = kclip ? (m0 + 256 < K ? m0 + 256 : K) : K;
    int KT = Keff >> 6;

    extern __shared__ char sm[];
    uint32_t sb = smem_u32(sm);

    int tid = threadIdx.x;
    int wid = tid >> 5, lane = tid & 31;
    int wm = (wid & 3) << 6;
    int wn = (wid >> 2) << 6;
    int g = lane >> 3, r = lane & 7;
    int aro = ((g & 1) << 3) + r, aco = (g >> 1) << 4;
    int bro = ((g >> 1) << 3) + r, bco = (g & 1) << 4;

    float acc[4][8][4];
    #pragma unroll
    for (int i = 0; i < 4; i++)
        #pragma unroll
        for (int j = 0; j < 8; j++)
            #pragma unroll
            for (int t = 0; t < 4; t++) acc[i][j][t] = 0.0f;

    // stage layout: A_hi 32K | A_lo 32K | B_hi 16K | B_lo 16K = 96K
    #define LOAD_STAGE(s, k0) do {                                             \
        uint32_t st = sb + (uint32_t)(s) * 98304u;                             \
        _Pragma("unroll")                                                      \
        for (int i = 0; i < 8; i++) {                                          \
            int idx = tid + (i << 8);                                          \
            int row = idx >> 3, c = idx & 7;                                   \
            uint32_t d = st + SW128((uint32_t)((row << 7) + (c << 4)));        \
            LL go = (LL)(m0 + row) * lda + (k0) + (c << 3);                    \
            CP16(d,          Ah_b + go);                                       \
            CP16(d + 32768u, Al_b + go);                                       \
        }                                                                      \
        _Pragma("unroll")                                                      \
        for (int i = 0; i < 4; i++) {                                          \
            int idx = tid + (i << 8);                                          \
            int row = idx >> 3, c = idx & 7;                                   \
            uint32_t d = st + 65536u + SW128((uint32_t)((row << 7) + (c << 4)));\
            LL go = (LL)(n0 + row) * ldb + (k0) + (c << 3);                    \
            CP16(d,          Bh_b + go);                                       \
            CP16(d + 16384u, Bl_b + go);                                       \
        }                                                                      \
    } while (0)

    LOAD_STAGE(0, 0);
    CP_COMMIT();

    for (int kt = 0; kt < KT; kt++) {
        CP_WAIT0();
        __syncthreads();
        if (kt + 1 < KT) {
            LOAD_STAGE((kt + 1) & 1, (kt + 1) << 6);
            CP_COMMIT();
        }

        uint32_t aB = sb + (uint32_t)(kt & 1) * 98304u;
        uint32_t bB = aB + 65536u;

        #pragma unroll
        for (int ks = 0; ks < 4; ks++) {
            int kb = ks << 5;
            uint32_t ah[4][4], al[4][4];
            #pragma unroll
            for (int mf = 0; mf < 4; mf++) {
                uint32_t off = SW128((uint32_t)((wm + (mf << 4) + aro) * 128 + kb + aco));
                ldsm_x4(aB + off,          ah[mf][0], ah[mf][1], ah[mf][2], ah[mf][3]);
                ldsm_x4(aB + 32768u + off, al[mf][0], al[mf][1], al[mf][2], al[mf][3]);
            }
            #pragma unroll
            for (int ng = 0; ng < 4; ng++) {
                uint32_t off = SW128((uint32_t)((wn + (ng << 4) + bro) * 128 + kb + bco));
                uint32_t bh0, bh1, bh2, bh3, bl0, bl1, bl2, bl3;
                ldsm_x4(bB + off,          bh0, bh1, bh2, bh3);
                ldsm_x4(bB + 16384u + off, bl0, bl1, bl2, bl3);
                #pragma unroll
                for (int mf = 0; mf < 4; mf++) {
                    float* c0 = acc[mf][(ng << 1)];
                    float* c1 = acc[mf][(ng << 1) + 1];
                    mma_bf16(c0, ah[mf], bh0, bh1);
                    mma_bf16(c1, ah[mf], bh2, bh3);
                    mma_bf16(c0, ah[mf], bl0, bl1);
                    mma_bf16(c1, ah[mf], bl2, bl3);
                    mma_bf16(c0, al[mf], bh0, bh1);
                    mma_bf16(c1, al[mf], bh2, bh3);
                }
            }
        }
    }

    // epilogue (direct from regs; no smem reuse)
    #pragma unroll
    for (int mf = 0; mf < 4; mf++) {
        int row = m0 + wm + (mf << 4) + (lane >> 2);
        #pragma unroll
        for (int nf = 0; nf < 8; nf++) {
            int col = n0 + wn + (nf << 3) + ((lane & 3) << 1);
            float* a = acc[mf][nf];
            if (EPI == 0) {
                float bx = bias[col], by = bias[col + 1];
                float* Cb = C + zo*soC + zi*siC;
                *(float2*)(Cb + (LL)row * ldc + col)       = make_float2(a[0] + bx, a[1] + by);
                *(float2*)(Cb + (LL)(row + 8) * ldc + col) = make_float2(a[2] + bx, a[3] + by);
            } else if (EPI == 1) {
                float* Cb = C + zo*soC + zi*siC;
                *(float2*)(Cb + (LL)row * ldc + col)       = make_float2(a[0], a[1]);
                *(float2*)(Cb + (LL)(row + 8) * ldc + col) = make_float2(a[2], a[3]);
            } else {
                bf16* Hb = Chi + zo*soC + zi*siC;
                bf16* Lb = Clo + zo*soC + zi*siC;
                bf16 h0, l0, h1, l1;
                splitw(a[0], h0, l0); splitw(a[1], h1, l1);
                uint32_t hp = ((uint32_t)__bfloat16_as_ushort(h1) << 16) | __bfloat16_as_ushort(h0);
                uint32_t lp = ((uint32_t)__bfloat16_as_ushort(l1) << 16) | __bfloat16_as_ushort(l0);
                *(uint32_t*)(Hb + (LL)row * ldc + col) = hp;
                *(uint32_t*)(Lb + (LL)row * ldc + col) = lp;
                splitw(a[2], h0, l0); splitw(a[3], h1, l1);
                hp = ((uint32_t)__bfloat16_as_ushort(h1) << 16) | __bfloat16_as_ushort(h0);
                lp = ((uint32_t)__bfloat16_as_ushort(l1) << 16) | __bfloat16_as_ushort(l0);
                *(uint32_t*)(Hb + (LL)(row + 8) * ldc + col) = hp;
                *(uint32_t*)(Lb + (LL)(row + 8) * ldc + col) = lp;
            }
        }
    }
}

// ---------------- score GEMM: 128x128, BK=32, 3-stage, 2 CTAs/SM ----------------
// w[m,n] per (b,h) = q . k, q pre-scaled. Causal: skip tiles with n0 > m0.
__global__ __launch_bounds__(256, 2)
void score_gemm(const bf16* __restrict__ Ahi, const bf16* __restrict__ Alo,
                const bf16* __restrict__ Bhi, const bf16* __restrict__ Blo,
                float* __restrict__ W)
{
    int m0 = blockIdx.y * 128;
    int n0 = blockIdx.x * 128;
    if (n0 > m0) return;

    int z = blockIdx.z;
    int b = z >> 4, hh = z & 15;
    const LL lda = (LL)N_HEADS * D_QK;
    LL abase = (LL)b * SEQ * lda + (LL)hh * D_QK;
    const bf16* Ah_b = Ahi + abase;
    const bf16* Al_b = Alo + abase;
    const bf16* Bh_b = Bhi + abase;
    const bf16* Bl_b = Blo + abase;
    float* Wb = W + (LL)z * SEQ * SEQ;

    extern __shared__ char sm[];
    uint32_t sb = smem_u32(sm);

    int tid = threadIdx.x;
    int wid = tid >> 5, lane = tid & 31;
    int wm = (wid & 3) << 5;     // 4 warps along m: 32 rows each
    int wn = (wid >> 2) << 6;    // 2 warps along n: 64 cols each
    int g = lane >> 3, r = lane & 7;
    int aro = ((g & 1) << 3) + r, aco = (g >> 1) << 4;
    int bro = ((g >> 1) << 3) + r, bco = (g & 1) << 4;

    float acc[2][8][4];
    #pragma unroll
    for (int i = 0; i < 2; i++)
        #pragma unroll
        for (int j = 0; j < 8; j++)
            #pragma unroll
            for (int t = 0; t < 4; t++) acc[i][j][t] = 0.0f;

    // stage: Ahi 8K | Alo 8K | Bhi 8K | Blo 8K = 32K; 3 stages
    #define SLOAD(s, k0) do {                                                  \
        uint32_t st = sb + (uint32_t)(s) * 32768u;                             \
        _Pragma("unroll")                                                      \
        for (int i = 0; i < 2; i++) {                                          \
            int idx = tid + (i << 8);                                          \
            int row = idx >> 2, c = (idx & 3) << 4;                            \
            uint32_t sw = SW64((uint32_t)((row << 6) + c));                    \
            LL goA = (LL)(m0 + row) * lda + (k0) + ((idx & 3) << 3);           \
            LL goB = (LL)(n0 + row) * lda + (k0) + ((idx & 3) << 3);           \
            CP16(st + sw,           Ah_b + goA);                               \
            CP16(st + 8192u + sw,   Al_b + goA);                               \
            CP16(st + 16384u + sw,  Bh_b + goB);                               \
            CP16(st + 24576u + sw,  Bl_b + goB);                               \
        }                                                                      \
    } while (0)

    const int KT = D_QK / 32;   // 6
    SLOAD(0, 0); CP_COMMIT();
    SLOAD(1, 32); CP_COMMIT();

    for (int kt = 0; kt < KT; kt++) {
        CP_WAIT1();
        __syncthreads();
        if (kt + 2 < KT) {
            int s = kt + 2; s -= (s >= 3) ? 3 : 0;
            SLOAD(s, (kt + 2) << 5);
            CP_COMMIT();
        }
        int cs = kt; cs -= (cs >= 3) ? 3 : 0; if (cs >= 3) cs -= 3;
        uint32_t aB = sb + (uint32_t)cs * 32768u;
        uint32_t bB = aB + 16384u;

        #pragma unroll
        for (int ks = 0; ks < 2; ks++) {
            int kb = ks << 5;
            uint32_t ah[2][4], al[2][4];
            #pragma unroll
            for (int mf = 0; mf < 2; mf++) {
                uint32_t off = SW64((uint32_t)((wm + (mf << 4) + aro) * 64 + kb + aco));
                ldsm_x4(aB + off,         ah[mf][0], ah[mf][1], ah[mf][2], ah[mf][3]);
                ldsm_x4(aB + 8192u + off, al[mf][0], al[mf][1], al[mf][2], al[mf][3]);
            }
            #pragma unroll
            for (int ng = 0; ng < 4; ng++) {
                uint32_t off = SW64((uint32_t)((wn + (ng << 4) + bro) * 64 + kb + bco));
                uint32_t bh0, bh1, bh2, bh3, bl0, bl1, bl2, bl3;
                ldsm_x4(bB + off,         bh0, bh1, bh2, bh3);
                ldsm_x4(bB + 8192u + off, bl0, bl1, bl2, bl3);
                #pragma unroll
                for (int mf = 0; mf < 2; mf++) {
                    float* c0 = acc[mf][(ng << 1)];
                    float* c1 = acc[mf][(ng << 1) + 1];
                    mma_bf16(c0, ah[mf], bh0, bh1);
                    mma_bf16(c1, ah[mf], bh2, bh3);
                    mma_bf16(c0, ah[mf], bl0, bl1);
                    mma_bf16(c1, ah[mf], bl2, bl3);
                    mma_bf16(c0, al[mf], bh0, bh1);
                    mma_bf16(c1, al[mf], bh2, bh3);
                }
            }
        }
    }

    #pragma unroll
    for (int mf = 0; mf < 2; mf++) {
        int row = m0 + wm + (mf << 4) + (lane >> 2);
        #pragma unroll
        for (int nf = 0; nf < 8; nf++) {
            int col = n0 + wn + (nf << 3) + ((lane & 3) << 1);
            float* a = acc[mf][nf];
            *(float2*)(Wb + (LL)row * SEQ + col)       = make_float2(a[0], a[1]);
            *(float2*)(Wb + (LL)(row + 8) * SEQ + col) = make_float2(a[2], a[3]);
        }
    }
}

// ---------------- split kernels ----------------
__global__ __launch_bounds__(256)
void split_rm(const float* __restrict__ x, bf16* __restrict__ hi, bf16* __restrict__ lo)
{
    LL base = ((LL)blockIdx.x * 256 + threadIdx.x) * 4;
    float4 v = *(const float4*)(x + base);
    bf16 h[4], l[4];
    splitw(v.x, h[0], l[0]); splitw(v.y, h[1], l[1]);
    splitw(v.z, h[2], l[2]); splitw(v.w, h[3], l[3]);
    *(uint2*)(hi + base) = *(uint2*)h;
    *(uint2*)(lo + base) = *(uint2*)l;
}

__global__ __launch_bounds__(256)
void split_tr(const float* __restrict__ x, bf16* __restrict__ hi, bf16* __restrict__ lo,
              int R, int C)
{
    __shared__ float s[32][33];
    int tx = threadIdx.x & 31, ty = threadIdx.x >> 5;
    int r0 = blockIdx.y * 32, c0 = blockIdx.x * 32;
    #pragma unroll
    for (int j = 0; j < 4; j++)
        s[ty + 8*j][tx] = x[(LL)(r0 + ty + 8*j) * C + c0 + tx];
    __syncthreads();
    #pragma unroll
    for (int j = 0; j < 4; j++) {
        float v = s[tx][ty + 8*j];
        bf16 h, l; splitw(v, h, l);
        LL o = (LL)(c0 + ty + 8*j) * R + r0 + tx;
        hi[o] = h; lo[o] = l;
    }
}

// ---------------- rmsnorm ----------------
__global__ __launch_bounds__(256)
void rmsnorm_kernel(const float* __restrict__ x, const float* __restrict__ g,
                    float* __restrict__ y, int dim)
{
    LL base = (LL)blockIdx.x * dim;
    int tid = threadIdx.x;
    float s = 0.0f;
    for (int i = tid; i < dim; i += 256) { float v = x[base + i]; s += v * v; }
    __shared__ float red[256];
    red[tid] = s; __syncthreads();
    for (int st = 128; st > 0; st >>= 1) {
        if (tid < st) red[tid] += red[tid + st];
        __syncthreads();
    }
    float rs = rsqrtf(red[0] / (float)dim + 1e-6f);
    for (int i = tid; i < dim; i += 256)
        y[base + i] = x[base + i] * rs * g[i];
}

__global__ __launch_bounds__(256)
void rmsnorm_split(const float* __restrict__ x, const float* __restrict__ g,
                   bf16* __restrict__ yh, bf16* __restrict__ yl, int dim)
{
    LL base = (LL)blockIdx.x * dim;
    int tid = threadIdx.x;
    float s = 0.0f;
    for (int i = tid; i < dim; i += 256) { float v = x[base + i]; s += v * v; }
    __shared__ float red[256];
    red[tid] = s; __syncthreads();
    for (int st = 128; st > 0; st >>= 1) {
        if (tid < st) red[tid] += red[tid + st];
        __syncthreads();
    }
    float rs = rsqrtf(red[0] / (float)dim + 1e-6f);
    for (int i = tid; i < dim; i += 256) {
        float v = x[base + i] * rs * g[i];
        bf16 h, l; splitw(v, h, l);
        yh[base + i] = h; yl[base + i] = l;
    }
}

// ---------------- pack with RoPE -> bf16 splits (q pre-scaled) ----------------
__global__ __launch_bounds__(256)
void pack_split(const float* __restrict__ qC, const float* __restrict__ qR,
                const float* __restrict__ krn, const float* __restrict__ kC,
                const float* __restrict__ freqs,
                bf16* __restrict__ qfh, bf16* __restrict__ qfl,
                bf16* __restrict__ kfh, bf16* __restrict__ kfl, float scale)
{
    int bs = blockIdx.x;
    int s  = bs & (SEQ - 1);
    LL qfb = (LL)bs * N_HEADS * D_QK;
    int tid = threadIdx.x;

    __shared__ float krs[D_R];
    if (tid < 32) {
        int i = tid;
        float a = krn[(LL)bs*D_R + 2*i];
        float b = krn[(LL)bs*D_R + 2*i + 1];
        float c  = freqs[(LL)s*D_R + 2*i];
        float sn = freqs[(LL)s*D_R + 2*i + 1];
        krs[2*i]   = a*c - b*sn;
        krs[2*i+1] = a*sn + b*c;
    }
    __syncthreads();

    for (int idx = tid; idx < N_HEADS*D_H; idx += 256) {
        int h = idx >> 7, d = idx & 127;
        float v = qC[(LL)bs*(N_HEADS*D_H) + idx] * scale;
        bf16 hh, ll; splitw(v, hh, ll);
        qfh[qfb + h*D_QK + d] = hh; qfl[qfb + h*D_QK + d] = ll;
    }
    for (int idx = tid; idx < N_HEADS*(D_R/2); idx += 256) {
        int h = idx >> 5, i = idx & 31;
        float a = qR[(LL)bs*(N_HEADS*D_R) + h*D_R + 2*i];
        float b = qR[(LL)bs*(N_HEADS*D_R) + h*D_R + 2*i + 1];
        float c  = freqs[(LL)s*D_R + 2*i];
        float sn = freqs[(LL)s*D_R + 2*i + 1];
        float v0 = (a*c - b*sn) * scale, v1 = (a*sn + b*c) * scale;
        bf16 hh, ll;
        splitw(v0, hh, ll);
        qfh[qfb + h*D_QK + D_H + 2*i] = hh;   qfl[qfb + h*D_QK + D_H + 2*i] = ll;
        splitw(v1, hh, ll);
        qfh[qfb + h*D_QK + D_H + 2*i+1] = hh; qfl[qfb + h*D_QK + D_H + 2*i+1] = ll;
    }
    for (int idx = tid; idx < N_HEADS*D_R; idx += 256) {
        int h = idx >> 6, d = idx & 63;
        bf16 hh, ll; splitw(krs[d], hh, ll);
        kfh[qfb + h*D_QK + d] = hh; kfl[qfb + h*D_QK + d] = ll;
    }
    for (int idx = tid; idx < N_HEADS*D_H; idx += 256) {
        int h = idx >> 7, d = idx & 127;
        float v = kC[(LL)bs*(N_HEADS*D_H) + idx];
        bf16 hh, ll; splitw(v, hh, ll);
        kfh[qfb + h*D_QK + D_R + d] = hh; kfl[qfb + h*D_QK + D_R + d] = ll;
    }
}

// ---------------- causal softmax + split emission (no masked reads) ----------------
__global__ __launch_bounds__(256)
void softmax_kernel(float* __restrict__ w, bf16* __restrict__ wh, bf16* __restrict__ wl)
{
    LL row = blockIdx.x;
    int q = (int)(row & (SEQ - 1));
    float* base = w + row * (LL)SEQ;
    bf16* bh = wh + row * (LL)SEQ;
    bf16* bl = wl + row * (LL)SEQ;
    int tid = threadIdx.x;

    float vals[8];
    float mx = -INFINITY;
    #pragma unroll
    for (int it = 0; it < 8; it++) {
        int k = tid + it * 256;
        float v = -INFINITY;
        if (k <= q) v = base[k];
        vals[it] = v;
        mx = fmaxf(mx, v);
    }
    __shared__ float red[256];
    red[tid] = mx; __syncthreads();
    for (int st = 128; st > 0; st >>= 1) {
        if (tid < st) red[tid] = fmaxf(red[tid], red[tid + st]);
        __syncthreads();
    }
    mx = red[0]; __syncthreads();

    float sum = 0.0f;
    #pragma unroll
    for (int it = 0; it < 8; it++) {
        float e = (vals[it] == -INFINITY) ? 0.0f : __expf(vals[it] - mx);
        vals[it] = e;
        sum += e;
    }
    red[tid] = sum; __syncthreads();
    for (int st = 128; st > 0; st >>= 1) {
        if (tid < st) red[tid] += red[tid + st];
        __syncthreads();
    }
    float inv = 1.0f / red[0];

    int kLim = ((q >> 8) + 1) << 8;   // what PV's K-clip reads
    #pragma unroll
    for (int it = 0; it < 8; it++) {
        int k = tid + it * 256;
        float p = vals[it] * inv;
        base[k] = p;
        if (k < kLim) {
            bf16 h, l; splitw(p, h, l);
            bh[k] = h; bl[k] = l;
        }
    }
}

// ---------------- scalar SGEMM for the tiny N=64 kr projection ----------------
__global__ __launch_bounds__(256)
void gemm_small(const float* __restrict__ A, const float* __restrict__ Bm,
                const float* __restrict__ bias, float* __restrict__ C,
                int K, int lda, int ldb, int ldc)
{
    int m0 = blockIdx.y * 64;
    int n0 = blockIdx.x * 64;
    __shared__ float sA[16][68];
    __shared__ float sB[16][68];
    int tid = threadIdx.x;
    int ty = tid >> 4, tx = tid & 15;
    float acc[4][4] = {};
    int arow = tid >> 2, ak = (tid & 3) * 4;
    int brow = tid >> 4, bcol = (tid & 15) * 4;

    for (int k0 = 0; k0 < K; k0 += 16) {
        float4 a4 = *(const float4*)(A + (LL)(m0 + arow) * lda + k0 + ak);
        sA[ak+0][arow] = a4.x; sA[ak+1][arow] = a4.y;
        sA[ak+2][arow] = a4.z; sA[ak+3][arow] = a4.w;
        float4 b4 = *(const float4*)(Bm + (LL)(k0 + brow) * ldb + n0 + bcol);
        *(float4*)&sB[brow][bcol] = b4;
        __syncthreads();
        #pragma unroll
        for (int kk = 0; kk < 16; kk++) {
            float af[4], bf[4];
            *(float4*)af = *(const float4*)&sA[kk][ty*4];
            *(float4*)bf = *(const float4*)&sB[kk][tx*4];
            #pragma unroll
            for (int i = 0; i < 4; i++)
                #pragma unroll
                for (int j = 0; j < 4; j++)
                    acc[i][j] = fmaf(af[i], bf[j], acc[i][j]);
        }
        __syncthreads();
    }
    #pragma unroll
    for (int i = 0; i < 4; i++)
        #pragma unroll
        for (int j = 0; j < 4; j++)
            C[(LL)(m0 + ty*4 + i) * ldc + n0 + tx*4 + j] = acc[i][j] + bias[n0 + tx*4 + j];
}

// ---------------- host ----------------
#define SYMF(name) ({ void* p_; cudaGetSymbolAddress(&p_, name); (float*)p_; })
#define SYMB(name) ({ void* p_; cudaGetSymbolAddress(&p_, name); (bf16*)p_; })

#define GEMM_SMEM 196608
#define SCORE_SMEM 98304

extern "C" void kernel_launch(void* const* d_in, const int* in_sizes, int n_in,
                              void* d_out, int out_size)
{
    (void)in_sizes; (void)n_in; (void)out_size;
    const float* h       = (const float*)d_in[0];
    const float* freqs   = (const float*)d_in[1];
    const float* Wq_down = (const float*)d_in[3];
    const float* bq_down = (const float*)d_in[4];
    const float* gq_norm = (const float*)d_in[5];
    const float* Wqc     = (const float*)d_in[6];
    const float* bqc     = (const float*)d_in[7];
    const float* Wqr     = (const float*)d_in[8];
    const float* bqr     = (const float*)d_in[9];
    const float* Wkr     = (const float*)d_in[10];
    const float* bkr     = (const float*)d_in[11];
    const float* gkr     = (const float*)d_in[12];
    const float* Wkv     = (const float*)d_in[13];
    const float* bkv     = (const float*)d_in[14];
    const float* gkv     = (const float*)d_in[15];
    const float* Wkc     = (const float*)d_in[16];
    const float* bkc     = (const float*)d_in[17];
    const float* Wvc     = (const float*)d_in[18];
    const float* bvc     = (const float*)d_in[19];
    const float* Wo      = (const float*)d_in[20];
    const float* bo      = (const float*)d_in[21];

    float* out_h = (float*)d_out;
    float* w     = out_h + (LL)NTOK * D_MODEL;

    float* tmp1 = SYMF(g_tmp1); float* tmp2 = SYMF(g_tmp2);
    float* qC = SYMF(g_qC);     float* qR = SYMF(g_qR);
    float* kr = SYMF(g_kr);     float* krn = SYMF(g_krn);
    float* kC = SYMF(g_kC);     float* vC = SYMF(g_vC);

    bf16 *h_hi = SYMB(g_h_hi), *h_lo = SYMB(g_h_lo);
    bf16 *WqdT_hi = SYMB(g_WqdT_hi), *WqdT_lo = SYMB(g_WqdT_lo);
    bf16 *WqcT_hi = SYMB(g_WqcT_hi), *WqcT_lo = SYMB(g_WqcT_lo);
    bf16 *WqrT_hi = SYMB(g_WqrT_hi), *WqrT_lo = SYMB(g_WqrT_lo);
    bf16 *WkvT_hi = SYMB(g_WkvT_hi), *WkvT_lo = SYMB(g_WkvT_lo);
    bf16 *WkcT_hi = SYMB(g_WkcT_hi), *WkcT_lo = SYMB(g_WkcT_lo);
    bf16 *WvcT_hi = SYMB(g_WvcT_hi), *WvcT_lo = SYMB(g_WvcT_lo);
    bf16 *WoT_hi  = SYMB(g_WoT_hi),  *WoT_lo  = SYMB(g_WoT_lo);
    bf16 *cQ_hi = SYMB(g_cQ_hi), *cQ_lo = SYMB(g_cQ_lo);
    bf16 *cKV_hi = SYMB(g_cKV_hi), *cKV_lo = SYMB(g_cKV_lo);
    bf16 *qf_hi = SYMB(g_qf_hi), *qf_lo = SYMB(g_qf_lo);
    bf16 *kf_hi = SYMB(g_kf_hi), *kf_lo = SYMB(g_kf_lo);
    bf16 *vCT_hi = SYMB(g_vCT_hi), *vCT_lo = SYMB(g_vCT_lo);
    bf16 *w_hi = SYMB(g_w_hi), *w_lo = SYMB(g_w_lo);
    bf16 *attn_hi = SYMB(g_attn_hi), *attn_lo = SYMB(g_attn_lo);

    cudaFuncSetAttribute(gemm_cp<0>, cudaFuncAttributeMaxDynamicSharedMemorySize, GEMM_SMEM);
    cudaFuncSetAttribute(gemm_cp<1>, cudaFuncAttributeMaxDynamicSharedMemorySize, GEMM_SMEM);
    cudaFuncSetAttribute(gemm_cp<2>, cudaFuncAttributeMaxDynamicSharedMemorySize, GEMM_SMEM);
    cudaFuncSetAttribute(score_gemm, cudaFuncAttributeMaxDynamicSharedMemorySize, SCORE_SMEM);

    // -------- operand splits --------
    split_rm<<<(LL)NTOK*D_MODEL/1024, 256>>>(h, h_hi, h_lo);
    split_tr<<<dim3(D_CQ/32, D_MODEL/32), 256>>>(Wq_down, WqdT_hi, WqdT_lo, D_MODEL, D_CQ);
    split_tr<<<dim3(2048/32, D_CQ/32), 256>>>(Wqc, WqcT_hi, WqcT_lo, D_CQ, 2048);
    split_tr<<<dim3(1024/32, D_CQ/32), 256>>>(Wqr, WqrT_hi, WqrT_lo, D_CQ, 1024);
    split_tr<<<dim3(D_C/32, D_MODEL/32), 256>>>(Wkv, WkvT_hi, WkvT_lo, D_MODEL, D_C);
    split_tr<<<dim3(2048/32, D_C/32), 256>>>(Wkc, WkcT_hi, WkcT_lo, D_C, 2048);
    split_tr<<<dim3(2048/32, D_C/32), 256>>>(Wvc, WvcT_hi, WvcT_lo, D_C, 2048);
    split_tr<<<dim3(2048/32, 2048/32), 256>>>(Wo, WoT_hi, WoT_lo, 2048, 2048);

    // -------- 1) cQ = rmsnorm(h @ Wq_down + b) --------
    gemm_cp<0><<<dim3(D_CQ/128, NTOK/256), 256, GEMM_SMEM>>>(
        h_hi, h_lo, WqdT_hi, WqdT_lo, bq_down, tmp1, nullptr, nullptr,
        D_MODEL, D_MODEL, D_MODEL, D_CQ, 0,0,0,0,0,0,1, 0);
    rmsnorm_split<<<NTOK, 256>>>(tmp1, gq_norm, cQ_hi, cQ_lo, D_CQ);

    // -------- 2) qC, qR --------
    gemm_cp<0><<<dim3(2048/128, NTOK/256), 256, GEMM_SMEM>>>(
        cQ_hi, cQ_lo, WqcT_hi, WqcT_lo, bqc, qC, nullptr, nullptr,
        D_CQ, D_CQ, D_CQ, 2048, 0,0,0,0,0,0,1, 0);
    gemm_cp<0><<<dim3(1024/128, NTOK/256), 256, GEMM_SMEM>>>(
        cQ_hi, cQ_lo, WqrT_hi, WqrT_lo, bqr, qR, nullptr, nullptr,
        D_CQ, D_CQ, D_CQ, 1024, 0,0,0,0,0,0,1, 0);

    // -------- 3) kr --------
    gemm_small<<<dim3(1, NTOK/64), 256>>>(h, Wkr, bkr, kr, D_MODEL, D_MODEL, D_R, D_R);
    rmsnorm_kernel<<<NTOK, 256>>>(kr, gkr, krn, D_R);

    // -------- 4) cKV --------
    gemm_cp<0><<<dim3(D_C/128, NTOK/256), 256, GEMM_SMEM>>>(
        h_hi, h_lo, WkvT_hi, WkvT_lo, bkv, tmp2, nullptr, nullptr,
        D_MODEL, D_MODEL, D_MODEL, D_C, 0,0,0,0,0,0,1, 0);
    rmsnorm_split<<<NTOK, 256>>>(tmp2, gkv, cKV_hi, cKV_lo, D_C);

    // -------- 5) kC, vC --------
    gemm_cp<0><<<dim3(2048/128, NTOK/256), 256, GEMM_SMEM>>>(
        cKV_hi, cKV_lo, WkcT_hi, WkcT_lo, bkc, kC, nullptr, nullptr,
        D_C, D_C, D_C, 2048, 0,0,0,0,0,0,1, 0);
    gemm_cp<0><<<dim3(2048/128, NTOK/256), 256, GEMM_SMEM>>>(
        cKV_hi, cKV_lo, WvcT_hi, WvcT_lo, bvc, vC, nullptr, nullptr,
        D_C, D_C, D_C, 2048, 0,0,0,0,0,0,1, 0);
    split_tr<<<dim3(2048/32, NTOK/32), 256>>>(vC, vCT_hi, vCT_lo, NTOK, 2048);

    // -------- 6) pack + RoPE (q pre-scaled) --------
    pack_split<<<NTOK, 256>>>(qC, qR, krn, kC, freqs, qf_hi, qf_lo, kf_hi, kf_lo,
                              1.0f / sqrtf((float)D_QK));

    // -------- 7) scores = q k^T (causal tiles, 2 CTAs/SM) --------
    score_gemm<<<dim3(SEQ/128, SEQ/128, BSZ*N_HEADS), 256, SCORE_SMEM>>>(
        qf_hi, qf_lo, kf_hi, kf_lo, w);

    // -------- 8) softmax (fp32 w + bf16 splits) --------
    softmax_kernel<<<(LL)BSZ*N_HEADS*SEQ, 256>>>(w, w_hi, w_lo);

    // -------- 9) attn = w @ vC (K clipped at diagonal), split output --------
    {
        LL soW = (LL)N_HEADS * SEQ * SEQ, siW = (LL)SEQ * SEQ;
        LL soB = 2048;
        LL siB = (LL)D_H * NTOK;
        LL soC = (LL)SEQ * 2048, siC = D_H;
        gemm_cp<2><<<dim3(D_H/128, SEQ/256, BSZ*N_HEADS), 256, GEMM_SMEM>>>(
            w_hi, w_lo, vCT_hi, vCT_lo, nullptr, nullptr, attn_hi, attn_lo,
            SEQ, SEQ, NTOK, 2048,
            soW, siW, soB, siB, soC, siC, N_HEADS, /*kclip=*/1);
    }

    // -------- 10) h_out = attn @ Wo + bo --------
    gemm_cp<0><<<dim3(2048/128, NTOK/256), 256, GEMM_SMEM>>>(
        attn_hi, attn_lo, WoT_hi, WoT_lo, bo, out_h, nullptr, nullptr,
        2048, 2048, 2048, 2048, 0,0,0,0,0,0,1, 0);
}